// round 11
// baseline (speedup 1.0000x reference)
#include <cuda_runtime.h>
#include <cuda_bf16.h>
#include <cstdint>
#include <math.h>

#define BB 8
#define NN 16384
#define KK 128
#define CC 128
#define LL 4
#define NSPLIT 16
#define XS (NN / NSPLIT)   // 1024
#define PAD 40
#define TSZ (128 * PAD)    // tile elems
#define TRS 132

typedef __nv_bfloat16 bf;

// ---------------- device scratch ----------------
__device__ bf g_bc[BB*NN*KK];
__device__ bf g_bs[BB*NN*KK];
__device__ bf g_wbc[BB*KK*NN];
__device__ bf g_wbs[BB*KK*NN];
__device__ bf g_hcnh[2][BB*CC*NN], g_hcnl[2][BB*CC*NN];
__device__ bf g_nch[BB*NN*CC], g_ncl[BB*NN*CC];
__device__ float g_pc[NSPLIT*BB*CC*KK], g_ps[NSPLIT*BB*CC*KK];
__device__ float g_xc[BB*CC*KK], g_xs[BB*CC*KK];
__device__ float g_x0v[BB*CC], g_f0v[BB*CC];
__device__ bf g_fcw[BB*CC*KK];
__device__ bf g_fsw[BB*CC*KK];
__device__ bf g_cw_hi[LL*CC*CC], g_cw_lo[LL*CC*CC];
__device__ bf g_w1t_hi[CC*CC], g_w1t_lo[CC*CC];

// ---------------- helpers ----------------
__device__ __forceinline__ void split_bf(float v, bf& h, bf& l) {
    h = __float2bfloat16(v);
    l = __float2bfloat16(v - __bfloat162float(h));
}
__device__ __forceinline__ float gelu_exact(float v) {
    return 0.5f * v * (1.0f + erff(v * 0.70710678118654752f));
}
#define MMA(d, a0, a1, a2, a3, b0, b1) \
    asm volatile("mma.sync.aligned.m16n8k16.row.col.f32.bf16.bf16.f32 " \
        "{%0,%1,%2,%3}, {%4,%5,%6,%7}, {%8,%9}, {%0,%1,%2,%3};" \
        : "+f"((d)[0]), "+f"((d)[1]), "+f"((d)[2]), "+f"((d)[3]) \
        : "r"(a0), "r"(a1), "r"(a2), "r"(a3), "r"(b0), "r"(b1))

__device__ __forceinline__ void cp_tile(bf* dst, const bf* __restrict__ src, size_t ldm, int tid) {
#pragma unroll
    for (int j = 0; j < 2; j++) {
        int idx = tid + j * 256;
        int row = idx >> 2, q = idx & 3;
        *(uint4*)(dst + row * PAD + q * 8) = *(const uint4*)(src + (size_t)row * ldm + q * 8);
    }
}

__device__ __forceinline__ void gemm_chunk1(const bf* A, const bf* B,
                                            float acc[4][4][4], int g, int tg, int m0, int n0) {
#pragma unroll
    for (int ks = 0; ks < 32; ks += 16) {
        uint32_t bh[4][2];
#pragma unroll
        for (int nt = 0; nt < 4; nt++) {
            const bf* p = B + (n0 + nt * 8 + g) * PAD + ks + tg * 2;
            bh[nt][0] = *(const uint32_t*)p;
            bh[nt][1] = *(const uint32_t*)(p + 8);
        }
#pragma unroll
        for (int mt = 0; mt < 4; mt++) {
            const bf* p = A + (m0 + mt * 16 + g) * PAD + ks + tg * 2;
            uint32_t a0 = *(const uint32_t*)p;
            uint32_t a1 = *(const uint32_t*)(p + 8 * PAD);
            uint32_t a2 = *(const uint32_t*)(p + 8);
            uint32_t a3 = *(const uint32_t*)(p + 8 * PAD + 8);
#pragma unroll
            for (int nt = 0; nt < 4; nt++)
                MMA(acc[mt][nt], a0, a1, a2, a3, bh[nt][0], bh[nt][1]);
        }
    }
}

// dual: shared A, two Bs, two accumulators (fused cos/sin forward projection)
__device__ __forceinline__ void gemm_chunk1_dual(const bf* A, const bf* Bc, const bf* Bs,
                                                 float accC[4][4][4], float accS[4][4][4],
                                                 int g, int tg, int m0, int n0) {
#pragma unroll
    for (int ks = 0; ks < 32; ks += 16) {
        uint32_t bc[4][2], bs[4][2];
#pragma unroll
        for (int nt = 0; nt < 4; nt++) {
            const bf* p = Bc + (n0 + nt * 8 + g) * PAD + ks + tg * 2;
            bc[nt][0] = *(const uint32_t*)p;
            bc[nt][1] = *(const uint32_t*)(p + 8);
            const bf* q = Bs + (n0 + nt * 8 + g) * PAD + ks + tg * 2;
            bs[nt][0] = *(const uint32_t*)q;
            bs[nt][1] = *(const uint32_t*)(q + 8);
        }
#pragma unroll
        for (int mt = 0; mt < 4; mt++) {
            const bf* p = A + (m0 + mt * 16 + g) * PAD + ks + tg * 2;
            uint32_t a0 = *(const uint32_t*)p;
            uint32_t a1 = *(const uint32_t*)(p + 8 * PAD);
            uint32_t a2 = *(const uint32_t*)(p + 8);
            uint32_t a3 = *(const uint32_t*)(p + 8 * PAD + 8);
#pragma unroll
            for (int nt = 0; nt < 4; nt++) {
                MMA(accC[mt][nt], a0, a1, a2, a3, bc[nt][0], bc[nt][1]);
                MMA(accS[mt][nt], a0, a1, a2, a3, bs[nt][0], bs[nt][1]);
            }
        }
    }
}

__device__ __forceinline__ void gemm_chunk3(const bf* Ah, const bf* Al, const bf* Bh, const bf* Bl,
                                            float acc[4][4][4], int g, int tg, int m0, int n0) {
#pragma unroll
    for (int ks = 0; ks < 32; ks += 16) {
        uint32_t bh[4][2], bl[4][2];
#pragma unroll
        for (int nt = 0; nt < 4; nt++) {
            const bf* p = Bh + (n0 + nt * 8 + g) * PAD + ks + tg * 2;
            bh[nt][0] = *(const uint32_t*)p;
            bh[nt][1] = *(const uint32_t*)(p + 8);
            const bf* q = Bl + (n0 + nt * 8 + g) * PAD + ks + tg * 2;
            bl[nt][0] = *(const uint32_t*)q;
            bl[nt][1] = *(const uint32_t*)(q + 8);
        }
#pragma unroll
        for (int mt = 0; mt < 4; mt++) {
            const bf* p = Ah + (m0 + mt * 16 + g) * PAD + ks + tg * 2;
            uint32_t ah0 = *(const uint32_t*)p;
            uint32_t ah1 = *(const uint32_t*)(p + 8 * PAD);
            uint32_t ah2 = *(const uint32_t*)(p + 8);
            uint32_t ah3 = *(const uint32_t*)(p + 8 * PAD + 8);
            const bf* q = Al + (m0 + mt * 16 + g) * PAD + ks + tg * 2;
            uint32_t al0 = *(const uint32_t*)q;
            uint32_t al1 = *(const uint32_t*)(q + 8 * PAD);
            uint32_t al2 = *(const uint32_t*)(q + 8);
            uint32_t al3 = *(const uint32_t*)(q + 8 * PAD + 8);
#pragma unroll
            for (int nt = 0; nt < 4; nt++) {
                MMA(acc[mt][nt], ah0, ah1, ah2, ah3, bh[nt][0], bh[nt][1]);
                MMA(acc[mt][nt], ah0, ah1, ah2, ah3, bl[nt][0], bl[nt][1]);
                MMA(acc[mt][nt], al0, al1, al2, al3, bh[nt][0], bh[nt][1]);
            }
        }
    }
}

// ---------------- producers ----------------
__global__ void bases_nk_kernel(const float* __restrict__ nodes, const float* __restrict__ mask,
                                const float* __restrict__ modes) {
    int gid = blockIdx.x * blockDim.x + threadIdx.x;
    int k = gid & (KK - 1);
    int bn = gid >> 7;
    float m = mask[bn];
    float t = nodes[bn*2] * __ldg(&modes[k*2]) + nodes[bn*2+1] * __ldg(&modes[k*2+1]);
    float s, c; sincosf(t, &s, &c);
    g_bc[gid] = __float2bfloat16(c * m);
    g_bs[gid] = __float2bfloat16(s * m);
}
__global__ void basesT_kernel(const float* __restrict__ nodes, const float* __restrict__ mask,
                              const float* __restrict__ nw, const float* __restrict__ modes) {
    __shared__ unsigned short Tc[KK*32], Tsn[KK*32];
    int n0 = blockIdx.x * 32, b = blockIdx.y, tid = threadIdx.x;
    for (int idx = tid; idx < KK*32; idx += 256) {
        int n = idx & 31, k = idx >> 5;
        int bn = b * NN + n0 + n;
        float f = mask[bn] * nw[bn];
        float t = nodes[bn*2] * __ldg(&modes[k*2]) + nodes[bn*2+1] * __ldg(&modes[k*2+1]);
        float s, c; sincosf(t, &s, &c);
        Tc[idx] = __bfloat16_as_ushort(__float2bfloat16(c * f));
        Tsn[idx] = __bfloat16_as_ushort(__float2bfloat16(s * f));
    }
    __syncthreads();
    for (int idx = tid; idx < KK*32; idx += 256) {
        int n = idx & 31, k = idx >> 5;
        size_t o = ((size_t)(b * KK + k)) * NN + n0 + n;
        g_wbc[o] = __ushort_as_bfloat16(Tc[idx]);
        g_wbs[o] = __ushort_as_bfloat16(Tsn[idx]);
    }
}
__global__ void fc0_kernel(const float* __restrict__ x, const float* __restrict__ w,
                           const float* __restrict__ bias,
                           bf* __restrict__ ohh, bf* __restrict__ ohl) {
    int gid = blockIdx.x * blockDim.x + threadIdx.x;
    int n = gid & (NN-1), c = (gid >> 14) & (CC-1), b = gid >> 21;
    const float* xp = x + ((size_t)b*NN + n)*3;
    float v = bias[c] + xp[0]*w[c] + xp[1]*w[CC+c] + xp[2]*w[2*CC+c];
    bf hi, lo; split_bf(v, hi, lo);
    ohh[gid] = hi; ohl[gid] = lo;
}
__global__ void split_weights_kernel(const float* __restrict__ convw, const float* __restrict__ fc1w) {
    int gid = blockIdx.x * blockDim.x + threadIdx.x;
    bf h, l;
    split_bf(convw[gid], h, l);
    g_cw_hi[gid] = h; g_cw_lo[gid] = l;
    if (gid < CC*CC) {
        int j = gid >> 7, c = gid & 127;
        split_bf(fc1w[c*CC + j], h, l);
        g_w1t_hi[gid] = h; g_w1t_lo[gid] = l;
    }
}
__global__ void trans_split(const bf* __restrict__ hh, const bf* __restrict__ hl) {
    __shared__ uint32_t T[32][33];
    int n0 = blockIdx.x * 32;
    int cb = blockIdx.y & 3;
    int b = blockIdx.y >> 2;
    int c0 = cb * 32;
    int tx = threadIdx.x & 31, ty = threadIdx.x >> 5;
#pragma unroll
    for (int i = 0; i < 4; i++) {
        int c = c0 + ty + i * 8;
        size_t off = ((size_t)b * CC + c) * NN + n0 + tx;
        T[ty + i * 8][tx] = (uint32_t)__bfloat16_as_ushort(hh[off])
                          | ((uint32_t)__bfloat16_as_ushort(hl[off]) << 16);
    }
    __syncthreads();
#pragma unroll
    for (int i = 0; i < 4; i++) {
        int n = n0 + ty + i * 8;
        uint32_t v = T[tx][ty + i * 8];
        size_t o = ((size_t)b * NN + n) * CC + c0 + tx;
        g_nch[o] = __ushort_as_bfloat16((unsigned short)(v & 0xffff));
        g_ncl[o] = __ushort_as_bfloat16((unsigned short)(v >> 16));
    }
}

// ---------------- fused forward projection (cos+sin), double-buffered ----------------
__global__ __launch_bounds__(256) void gemm_fwd2(const bf* __restrict__ Ahg) {
    extern __shared__ bf tiles[];   // [2][3][TSZ]: A, Bc, Bs
    int split = blockIdx.x, b = blockIdx.y;
    int tid = threadIdx.x, w = tid >> 5, lane = tid & 31, g = lane >> 2, tg = lane & 3;
    int m0 = (w & 1) * 64, n0 = (w >> 1) * 32;
    const bf* As_g = Ahg + (size_t)b * CC * NN + (size_t)split * XS;
    const bf* Bc_g = g_wbc + (size_t)b * KK * NN + (size_t)split * XS;
    const bf* Bs_g = g_wbs + (size_t)b * KK * NN + (size_t)split * XS;
    float accC[4][4][4], accS[4][4][4];
#pragma unroll
    for (int i = 0; i < 4; i++)
#pragma unroll
        for (int j = 0; j < 4; j++)
#pragma unroll
            for (int q = 0; q < 4; q++) { accC[i][j][q] = 0.f; accS[i][j][q] = 0.f; }

    const int NCH = XS / 32;   // 32
    // prime buffer 0
    cp_tile(tiles + 0*3*TSZ + 0*TSZ, As_g, NN, tid);
    cp_tile(tiles + 0*3*TSZ + 1*TSZ, Bc_g, NN, tid);
    cp_tile(tiles + 0*3*TSZ + 2*TSZ, Bs_g, NN, tid);
    __syncthreads();
    for (int ch = 0; ch < NCH; ch++) {
        int cur = ch & 1, nxt = cur ^ 1;
        if (ch + 1 < NCH) {
            int x0 = (ch + 1) * 32;
            cp_tile(tiles + nxt*3*TSZ + 0*TSZ, As_g + x0, NN, tid);
            cp_tile(tiles + nxt*3*TSZ + 1*TSZ, Bc_g + x0, NN, tid);
            cp_tile(tiles + nxt*3*TSZ + 2*TSZ, Bs_g + x0, NN, tid);
        }
        const bf* base = tiles + cur*3*TSZ;
        gemm_chunk1_dual(base, base + TSZ, base + 2*TSZ, accC, accS, g, tg, m0, n0);
        __syncthreads();
    }
    float* pc = g_pc + (size_t)(split * BB + b) * CC * KK;
    float* ps = g_ps + (size_t)(split * BB + b) * CC * KK;
#pragma unroll
    for (int mt = 0; mt < 4; mt++) {
        int r0 = m0 + mt * 16 + g;
#pragma unroll
        for (int nt = 0; nt < 4; nt++) {
            int n = n0 + nt * 8 + tg * 2;
            *(float2*)&pc[r0 * KK + n] = make_float2(accC[mt][nt][0], accC[mt][nt][1]);
            *(float2*)&pc[(r0 + 8) * KK + n] = make_float2(accC[mt][nt][2], accC[mt][nt][3]);
            *(float2*)&ps[r0 * KK + n] = make_float2(accS[mt][nt][0], accS[mt][nt][1]);
            *(float2*)&ps[(r0 + 8) * KK + n] = make_float2(accS[mt][nt][2], accS[mt][nt][3]);
        }
    }
}

// ---------------- fused inverse (double-buffered): spectral + conv; writes hcn AND hnc ----------------
__global__ __launch_bounds__(256) void inv3(const bf* __restrict__ hnc_hi, const bf* __restrict__ hnc_lo,
                                            bf* __restrict__ ohh, bf* __restrict__ ohl,
                                            bf* __restrict__ onch, bf* __restrict__ oncl,
                                            const float* __restrict__ convb,
                                            const float* __restrict__ mask,
                                            int l, int apply_gelu) {
    extern __shared__ bf tiles[];   // [2][4][TSZ]; Tr overlays after MMA
    uint32_t* Tr = (uint32_t*)tiles;
    int xb = blockIdx.x * 128, b = blockIdx.y;
    int tid = threadIdx.x, w = tid >> 5, lane = tid & 31, g = lane >> 2, tg = lane & 3;
    int m0 = (w & 1) * 64, n0 = (w >> 1) * 32;
    float acc[4][4][4];
#pragma unroll
    for (int i = 0; i < 4; i++)
#pragma unroll
        for (int j = 0; j < 4; j++)
#pragma unroll
            for (int q = 0; q < 4; q++) acc[i][j][q] = 0.f;

    const bf* pA01[2] = { g_fcw + (size_t)b*CC*KK, g_fsw + (size_t)b*CC*KK };
    const bf* pB01[2] = { g_bc + ((size_t)b*NN + xb)*KK, g_bs + ((size_t)b*NN + xb)*KK };
    const bf* cAh = g_cw_hi + (size_t)l*CC*CC;
    const bf* cAl = g_cw_lo + (size_t)l*CC*CC;
    const bf* cBh = hnc_hi + ((size_t)b*NN + xb)*CC;
    const bf* cBl = hnc_lo + ((size_t)b*NN + xb)*CC;

    auto load_step = [&](int s, int buf) {
        bf* base = tiles + (size_t)buf * 4 * TSZ;
        if (s < 8) {
            int pass = s >> 2, ch = s & 3;
            cp_tile(base + 0*TSZ, pA01[pass] + ch * 32, 128, tid);
            cp_tile(base + 2*TSZ, pB01[pass] + ch * 32, 128, tid);
        } else {
            int ch = s - 8;
            cp_tile(base + 0*TSZ, cAh + ch * 32, 128, tid);
            cp_tile(base + 1*TSZ, cAl + ch * 32, 128, tid);
            cp_tile(base + 2*TSZ, cBh + ch * 32, 128, tid);
            cp_tile(base + 3*TSZ, cBl + ch * 32, 128, tid);
        }
    };
    load_step(0, 0);
    __syncthreads();
    for (int s = 0; s < 12; s++) {
        int cur = s & 1;
        if (s + 1 < 12) load_step(s + 1, cur ^ 1);
        bf* base = tiles + (size_t)cur * 4 * TSZ;
        if (s < 8) gemm_chunk1(base, base + 2*TSZ, acc, g, tg, m0, n0);
        else gemm_chunk3(base, base + TSZ, base + 2*TSZ, base + 3*TSZ, acc, g, tg, m0, n0);
        __syncthreads();
    }
    // epilogue
#pragma unroll
    for (int mt = 0; mt < 4; mt++) {
        int r0 = m0 + mt * 16 + g, r1 = r0 + 8;
        float cb0 = convb[l * CC + r0], f00 = g_f0v[b * CC + r0];
        float cb1 = convb[l * CC + r1], f01 = g_f0v[b * CC + r1];
#pragma unroll
        for (int nt = 0; nt < 4; nt++) {
            int n = n0 + nt * 8 + tg * 2;
            float mk0 = mask[(size_t)b * NN + xb + n];
            float mk1 = mask[(size_t)b * NN + xb + n + 1];
            float v00 = acc[mt][nt][0] + cb0 + f00 * mk0;
            float v01 = acc[mt][nt][1] + cb0 + f00 * mk1;
            float v10 = acc[mt][nt][2] + cb1 + f01 * mk0;
            float v11 = acc[mt][nt][3] + cb1 + f01 * mk1;
            if (apply_gelu) {
                v00 = gelu_exact(v00); v01 = gelu_exact(v01);
                v10 = gelu_exact(v10); v11 = gelu_exact(v11);
            }
            bf h00, l00, h01, l01, h10, l10, h11, l11;
            split_bf(v00, h00, l00); split_bf(v01, h01, l01);
            split_bf(v10, h10, l10); split_bf(v11, h11, l11);
            uint32_t p00 = (uint32_t)__bfloat16_as_ushort(h00) | ((uint32_t)__bfloat16_as_ushort(l00) << 16);
            uint32_t p01 = (uint32_t)__bfloat16_as_ushort(h01) | ((uint32_t)__bfloat16_as_ushort(l01) << 16);
            uint32_t p10 = (uint32_t)__bfloat16_as_ushort(h10) | ((uint32_t)__bfloat16_as_ushort(l10) << 16);
            uint32_t p11 = (uint32_t)__bfloat16_as_ushort(h11) | ((uint32_t)__bfloat16_as_ushort(l11) << 16);
            size_t o0 = ((size_t)b * CC + r0) * NN + xb + n;
            size_t o1 = ((size_t)b * CC + r1) * NN + xb + n;
            *(uint32_t*)(ohh + o0) = (uint32_t)__bfloat16_as_ushort(h00) | ((uint32_t)__bfloat16_as_ushort(h01) << 16);
            *(uint32_t*)(ohl + o0) = (uint32_t)__bfloat16_as_ushort(l00) | ((uint32_t)__bfloat16_as_ushort(l01) << 16);
            *(uint32_t*)(ohh + o1) = (uint32_t)__bfloat16_as_ushort(h10) | ((uint32_t)__bfloat16_as_ushort(h11) << 16);
            *(uint32_t*)(ohl + o1) = (uint32_t)__bfloat16_as_ushort(l10) | ((uint32_t)__bfloat16_as_ushort(l11) << 16);
            Tr[n * TRS + r0]       = p00;
            Tr[(n + 1) * TRS + r0] = p01;
            Tr[n * TRS + r1]       = p10;
            Tr[(n + 1) * TRS + r1] = p11;
        }
    }
    __syncthreads();
    {
        int xq = tid >> 1;
        int c0t = (tid & 1) * 64;
        size_t ob = ((size_t)b * NN + xb + xq) * CC + c0t;
#pragma unroll
        for (int q = 0; q < 8; q++) {
            __align__(16) unsigned short hh8[8], ll8[8];
#pragma unroll
            for (int c = 0; c < 8; c++) {
                uint32_t v = Tr[xq * TRS + c0t + q * 8 + c];
                hh8[c] = (unsigned short)(v & 0xffff);
                ll8[c] = (unsigned short)(v >> 16);
            }
            *(uint4*)(onch + ob + q * 8) = *(uint4*)hh8;
            *(uint4*)(oncl + ob + q * 8) = *(uint4*)ll8;
        }
    }
}

// ---------------- small kernels ----------------
__global__ void reduce_kernel() {
    int gid = blockIdx.x * blockDim.x + threadIdx.x;
    float sc = 0.f, ss = 0.f;
#pragma unroll
    for (int s = 0; s < NSPLIT; s++) {
        sc += g_pc[(size_t)s * BB * CC * KK + gid];
        ss += g_ps[(size_t)s * BB * CC * KK + gid];
    }
    g_xc[gid] = sc;
    g_xs[gid] = -ss;
}
__global__ void x0_kernel(const bf* __restrict__ hh,
                          const float* __restrict__ nw, const float* __restrict__ mask) {
    int i = blockIdx.x, b = blockIdx.y;
    const bf* rh = hh + ((size_t)b * CC + i) * NN;
    const float* nwb = nw + b * NN;
    const float* mb = mask + b * NN;
    float acc = 0.f;
    for (int x = threadIdx.x; x < NN; x += 256)
        acc += __bfloat162float(rh[x]) * nwb[x] * mb[x];
    __shared__ float red[256];
    red[threadIdx.x] = acc;
    __syncthreads();
    for (int s = 128; s > 0; s >>= 1) {
        if (threadIdx.x < s) red[threadIdx.x] += red[threadIdx.x + s];
        __syncthreads();
    }
    if (threadIdx.x == 0) g_x0v[b * CC + i] = red[0];
}
__global__ void f0_kernel(const float* __restrict__ w0, int l) {
    int b = blockIdx.x, o = threadIdx.x;
    __shared__ float xs[CC];
    xs[o] = g_x0v[b * CC + o];
    __syncthreads();
    const float* w = w0 + (size_t)l * CC * CC;
    float acc = 0.f;
#pragma unroll 8
    for (int i = 0; i < CC; i++) acc += xs[i] * w[i * CC + o];
    g_f0v[b * CC + o] = acc;
}
__global__ void mix_kernel(const float* __restrict__ wc, const float* __restrict__ ws, int l) {
    int o = blockIdx.x, b = blockIdx.y, k = threadIdx.x;
    const float* wcl = wc + (size_t)l * CC * CC * KK;
    const float* wsl = ws + (size_t)l * CC * CC * KK;
    float fcA = 0.f, fsA = 0.f;
#pragma unroll 4
    for (int i = 0; i < CC; i++) {
        float xc = g_xc[(b * CC + i) * KK + k];
        float xv = g_xs[(b * CC + i) * KK + k];
        float wcv = wcl[((size_t)i * CC + o) * KK + k];
        float wsv = wsl[((size_t)i * CC + o) * KK + k];
        fcA += xc * wcv - xv * wsv;
        fsA += xv * wcv + xc * wsv;
    }
    int idx = (b * CC + o) * KK + k;
    g_fcw[idx] = __float2bfloat16(2.0f * fcA);
    g_fsw[idx] = __float2bfloat16(-2.0f * fsA);
}

// ---------------- fused fc1 (MMA split, double-buffered) + fc2 + mask ----------------
__global__ __launch_bounds__(256) void fc1fc2(const bf* __restrict__ hnc_hi, const bf* __restrict__ hnc_lo,
                                              const float* __restrict__ b1,
                                              const float* __restrict__ w2,
                                              const float* __restrict__ b2,
                                              const float* __restrict__ mask,
                                              float* __restrict__ out) {
    extern __shared__ bf tiles[];   // [2][4][TSZ]; Tsm overlays after MMA
    float* Tsm = (float*)tiles;
    float* w2s = (float*)((char*)tiles + 2 * 4 * TSZ * sizeof(bf));
    float* part = w2s + 128;
    int xb = blockIdx.x * 128, b = blockIdx.y;
    int tid = threadIdx.x, w = tid >> 5, lane = tid & 31, g = lane >> 2, tg = lane & 3;
    int m0 = (w & 1) * 64, n0 = (w >> 1) * 32;
    if (tid < 128) w2s[tid] = w2[tid];
    const bf* pBh = hnc_hi + ((size_t)b * NN + xb) * CC;
    const bf* pBl = hnc_lo + ((size_t)b * NN + xb) * CC;
    float acc[4][4][4];
#pragma unroll
    for (int i = 0; i < 4; i++)
#pragma unroll
        for (int j = 0; j < 4; j++)
#pragma unroll
            for (int q = 0; q < 4; q++) acc[i][j][q] = 0.f;

    auto load_step = [&](int ch, int buf) {
        bf* base = tiles + (size_t)buf * 4 * TSZ;
        cp_tile(base + 0*TSZ, g_w1t_hi + ch * 32, 128, tid);
        cp_tile(base + 1*TSZ, g_w1t_lo + ch * 32, 128, tid);
        cp_tile(base + 2*TSZ, pBh + ch * 32, 128, tid);
        cp_tile(base + 3*TSZ, pBl + ch * 32, 128, tid);
    };
    load_step(0, 0);
    __syncthreads();
    for (int ch = 0; ch < 4; ch++) {
        int cur = ch & 1;
        if (ch + 1 < 4) load_step(ch + 1, cur ^ 1);
        bf* base = tiles + (size_t)cur * 4 * TSZ;
        gemm_chunk3(base, base + TSZ, base + 2*TSZ, base + 3*TSZ, acc, g, tg, m0, n0);
        __syncthreads();
    }
#pragma unroll
    for (int mt = 0; mt < 4; mt++) {
        int r0 = m0 + mt * 16 + g, r1 = r0 + 8;
        float bb0 = b1[r0], bb8 = b1[r1];
#pragma unroll
        for (int nt = 0; nt < 4; nt++) {
            int n = n0 + nt * 8 + tg * 2;
            Tsm[n * TRS + r0]       = gelu_exact(acc[mt][nt][0] + bb0);
            Tsm[(n + 1) * TRS + r0] = gelu_exact(acc[mt][nt][1] + bb0);
            Tsm[n * TRS + r1]       = gelu_exact(acc[mt][nt][2] + bb8);
            Tsm[(n + 1) * TRS + r1] = gelu_exact(acc[mt][nt][3] + bb8);
        }
    }
    __syncthreads();
    {
        int xq = tid >> 1;
        int jh = (tid & 1) * 64;
        float p = 0.f;
#pragma unroll 8
        for (int j = 0; j < 64; j++)
            p += Tsm[xq * TRS + jh + j] * w2s[jh + j];
        part[tid] = p;
        __syncthreads();
        if ((tid & 1) == 0) {
            size_t xi = (size_t)b * NN + xb + xq;
            out[xi] = (part[tid] + part[tid + 1] + b2[0]) * mask[xi];
        }
    }
}

// ---------------- launch ----------------
extern "C" void kernel_launch(void* const* d_in, const int* in_sizes, int n_in,
                              void* d_out, int out_size) {
    const float* x     = (const float*)d_in[0];
    const float* nodes = (const float*)d_in[1];
    const float* mask  = (const float*)d_in[2];
    const float* nw    = (const float*)d_in[3];
    const float* modes = (const float*)d_in[4];
    const float* fc0w  = (const float*)d_in[5];
    const float* fc0b  = (const float*)d_in[6];
    const float* wc    = (const float*)d_in[7];
    const float* ws_   = (const float*)d_in[8];
    const float* w0    = (const float*)d_in[9];
    const float* convw = (const float*)d_in[10];
    const float* convb = (const float*)d_in[11];
    const float* fc1w  = (const float*)d_in[12];
    const float* fc1b  = (const float*)d_in[13];
    const float* fc2w  = (const float*)d_in[14];
    const float* fc2b  = (const float*)d_in[15];
    float* out = (float*)d_out;

    const int FWD_SMEM = 2 * 3 * TSZ * 2;                 // 61440
    const int INV_SMEM = 2 * 4 * TSZ * 2;                 // 81920 (>= Tr 67584)
    const int FC_SMEM  = 2 * 4 * TSZ * 2 + (128 + 256) * 4;   // 83456
    cudaFuncSetAttribute(gemm_fwd2, cudaFuncAttributeMaxDynamicSharedMemorySize, FWD_SMEM);
    cudaFuncSetAttribute(inv3, cudaFuncAttributeMaxDynamicSharedMemorySize, INV_SMEM);
    cudaFuncSetAttribute(fc1fc2, cudaFuncAttributeMaxDynamicSharedMemorySize, FC_SMEM);

    bf *nch, *ncl, *hh0, *hl0;
    cudaGetSymbolAddress((void**)&nch, g_nch);
    cudaGetSymbolAddress((void**)&ncl, g_ncl);
    cudaGetSymbolAddress((void**)&hh0, g_hcnh);
    cudaGetSymbolAddress((void**)&hl0, g_hcnl);
    bf* hh1 = hh0 + (size_t)BB*CC*NN;
    bf* hl1 = hl0 + (size_t)BB*CC*NN;

    bases_nk_kernel<<<(BB*NN*KK)/256, 256>>>(nodes, mask, modes);
    basesT_kernel<<<dim3(NN/32, BB), 256>>>(nodes, mask, nw, modes);
    fc0_kernel<<<(BB*CC*NN)/256, 256>>>(x, fc0w, fc0b, hh0, hl0);
    split_weights_kernel<<<(LL*CC*CC)/256, 256>>>(convw, fc1w);
    trans_split<<<dim3(NN/32, 4*BB), 256>>>(hh0, hl0);

    bf *ch = hh0, *cl = hl0, *oh = hh1, *ol = hl1;
    for (int l = 0; l < LL; l++) {
        gemm_fwd2<<<dim3(NSPLIT, BB), 256, FWD_SMEM>>>(ch);
        reduce_kernel<<<(BB*CC*KK)/256, 256>>>();
        x0_kernel<<<dim3(CC, BB), 256>>>(ch, nw, mask);
        f0_kernel<<<BB, CC>>>(w0, l);
        mix_kernel<<<dim3(CC, BB), KK>>>(wc, ws_, l);
        inv3<<<dim3(NN/128, BB), 256, INV_SMEM>>>(nch, ncl, oh, ol, nch, ncl,
                                                  convb, mask, l, (l != LL-1) ? 1 : 0);
        bf* t;
        t = ch; ch = oh; oh = t;
        t = cl; cl = ol; ol = t;
    }
    fc1fc2<<<dim3(NN/128, BB), 256, FC_SMEM>>>(nch, ncl, fc1b, fc2w, fc2b, mask, out);
}

// round 12
// speedup vs baseline: 1.1714x; 1.1714x over previous
#include <cuda_runtime.h>
#include <cuda_bf16.h>
#include <cstdint>
#include <math.h>

#define BB 8
#define NN 16384
#define KK 128
#define CC 128
#define LL 4
#define NSPLIT 32
#define XS (NN / NSPLIT)   // 512
#define PAD 40
#define TRS 132

typedef __nv_bfloat16 bf;

// ---------------- device scratch ----------------
__device__ bf g_bc[BB*NN*KK];
__device__ bf g_bs[BB*NN*KK];
__device__ bf g_wbc[BB*KK*NN];
__device__ bf g_wbs[BB*KK*NN];
__device__ bf g_hcnh[2][BB*CC*NN], g_hcnl[2][BB*CC*NN];
__device__ bf g_nch[BB*NN*CC], g_ncl[BB*NN*CC];
__device__ float g_pc[NSPLIT*BB*CC*KK], g_ps[NSPLIT*BB*CC*KK];
__device__ float g_xc[BB*CC*KK], g_xs[BB*CC*KK];
__device__ float g_x0v[BB*CC], g_f0v[BB*CC];
__device__ bf g_fcw[BB*CC*KK];
__device__ bf g_fsw[BB*CC*KK];
__device__ bf g_cw_hi[LL*CC*CC], g_cw_lo[LL*CC*CC];
__device__ bf g_w1t_hi[CC*CC], g_w1t_lo[CC*CC];

// ---------------- helpers ----------------
__device__ __forceinline__ void split_bf(float v, bf& h, bf& l) {
    h = __float2bfloat16(v);
    l = __float2bfloat16(v - __bfloat162float(h));
}
__device__ __forceinline__ float gelu_exact(float v) {
    return 0.5f * v * (1.0f + erff(v * 0.70710678118654752f));
}
#define MMA(d, a0, a1, a2, a3, b0, b1) \
    asm volatile("mma.sync.aligned.m16n8k16.row.col.f32.bf16.bf16.f32 " \
        "{%0,%1,%2,%3}, {%4,%5,%6,%7}, {%8,%9}, {%0,%1,%2,%3};" \
        : "+f"((d)[0]), "+f"((d)[1]), "+f"((d)[2]), "+f"((d)[3]) \
        : "r"(a0), "r"(a1), "r"(a2), "r"(a3), "r"(b0), "r"(b1))

__device__ __forceinline__ void cp_tile(bf* dst, const bf* __restrict__ src, size_t ldm, int tid) {
#pragma unroll
    for (int j = 0; j < 2; j++) {
        int idx = tid + j * 256;
        int row = idx >> 2, q = idx & 3;
        *(uint4*)(dst + row * PAD + q * 8) = *(const uint4*)(src + (size_t)row * ldm + q * 8);
    }
}

__device__ __forceinline__ void gemm_chunk1(const bf* A, const bf* B,
                                            float acc[4][4][4], int g, int tg, int m0, int n0) {
#pragma unroll
    for (int ks = 0; ks < 32; ks += 16) {
        uint32_t bh[4][2];
#pragma unroll
        for (int nt = 0; nt < 4; nt++) {
            const bf* p = B + (n0 + nt * 8 + g) * PAD + ks + tg * 2;
            bh[nt][0] = *(const uint32_t*)p;
            bh[nt][1] = *(const uint32_t*)(p + 8);
        }
#pragma unroll
        for (int mt = 0; mt < 4; mt++) {
            const bf* p = A + (m0 + mt * 16 + g) * PAD + ks + tg * 2;
            uint32_t a0 = *(const uint32_t*)p;
            uint32_t a1 = *(const uint32_t*)(p + 8 * PAD);
            uint32_t a2 = *(const uint32_t*)(p + 8);
            uint32_t a3 = *(const uint32_t*)(p + 8 * PAD + 8);
#pragma unroll
            for (int nt = 0; nt < 4; nt++)
                MMA(acc[mt][nt], a0, a1, a2, a3, bh[nt][0], bh[nt][1]);
        }
    }
}

__device__ __forceinline__ void gemm_chunk3(const bf* Ah, const bf* Al, const bf* Bh, const bf* Bl,
                                            float acc[4][4][4], int g, int tg, int m0, int n0) {
#pragma unroll
    for (int ks = 0; ks < 32; ks += 16) {
        uint32_t bh[4][2], bl[4][2];
#pragma unroll
        for (int nt = 0; nt < 4; nt++) {
            const bf* p = Bh + (n0 + nt * 8 + g) * PAD + ks + tg * 2;
            bh[nt][0] = *(const uint32_t*)p;
            bh[nt][1] = *(const uint32_t*)(p + 8);
            const bf* q = Bl + (n0 + nt * 8 + g) * PAD + ks + tg * 2;
            bl[nt][0] = *(const uint32_t*)q;
            bl[nt][1] = *(const uint32_t*)(q + 8);
        }
#pragma unroll
        for (int mt = 0; mt < 4; mt++) {
            const bf* p = Ah + (m0 + mt * 16 + g) * PAD + ks + tg * 2;
            uint32_t ah0 = *(const uint32_t*)p;
            uint32_t ah1 = *(const uint32_t*)(p + 8 * PAD);
            uint32_t ah2 = *(const uint32_t*)(p + 8);
            uint32_t ah3 = *(const uint32_t*)(p + 8 * PAD + 8);
            const bf* q = Al + (m0 + mt * 16 + g) * PAD + ks + tg * 2;
            uint32_t al0 = *(const uint32_t*)q;
            uint32_t al1 = *(const uint32_t*)(q + 8 * PAD);
            uint32_t al2 = *(const uint32_t*)(q + 8);
            uint32_t al3 = *(const uint32_t*)(q + 8 * PAD + 8);
#pragma unroll
            for (int nt = 0; nt < 4; nt++) {
                MMA(acc[mt][nt], ah0, ah1, ah2, ah3, bh[nt][0], bh[nt][1]);
                MMA(acc[mt][nt], ah0, ah1, ah2, ah3, bl[nt][0], bl[nt][1]);
                MMA(acc[mt][nt], al0, al1, al2, al3, bh[nt][0], bh[nt][1]);
            }
        }
    }
}

// ---------------- merged bases producer: bc/bs [n][k] + wbc/wbs [k][n] ----------------
__global__ void bases_all(const float* __restrict__ nodes, const float* __restrict__ mask,
                          const float* __restrict__ nw, const float* __restrict__ modes) {
    __shared__ unsigned short Tc[KK*32], Tsn[KK*32];
    int n0 = blockIdx.x * 32, b = blockIdx.y, tid = threadIdx.x;
    for (int idx = tid; idx < 32 * KK; idx += 256) {
        int n = idx >> 7, k = idx & 127;
        int bn = b * NN + n0 + n;
        float m = mask[bn];
        float wgt = m * nw[bn];
        float t = nodes[bn*2] * __ldg(&modes[k*2]) + nodes[bn*2+1] * __ldg(&modes[k*2+1]);
        float s, c; sincosf(t, &s, &c);
        size_t o = (size_t)bn * KK + k;
        g_bc[o] = __float2bfloat16(c * m);
        g_bs[o] = __float2bfloat16(s * m);
        Tc[k * 32 + n]  = __bfloat16_as_ushort(__float2bfloat16(c * wgt));
        Tsn[k * 32 + n] = __bfloat16_as_ushort(__float2bfloat16(s * wgt));
    }
    __syncthreads();
    for (int idx = tid; idx < KK * 32; idx += 256) {
        int n = idx & 31, k = idx >> 5;
        size_t o = ((size_t)(b * KK + k)) * NN + n0 + n;
        g_wbc[o] = __ushort_as_bfloat16(Tc[k * 32 + n]);
        g_wbs[o] = __ushort_as_bfloat16(Tsn[k * 32 + n]);
    }
}
__global__ void fc0_kernel(const float* __restrict__ x, const float* __restrict__ w,
                           const float* __restrict__ bias,
                           bf* __restrict__ ohh, bf* __restrict__ ohl) {
    int gid = blockIdx.x * blockDim.x + threadIdx.x;
    int n = gid & (NN-1), c = (gid >> 14) & (CC-1), b = gid >> 21;
    const float* xp = x + ((size_t)b*NN + n)*3;
    float v = bias[c] + xp[0]*w[c] + xp[1]*w[CC+c] + xp[2]*w[2*CC+c];
    bf hi, lo; split_bf(v, hi, lo);
    ohh[gid] = hi; ohl[gid] = lo;
}
__global__ void split_weights_kernel(const float* __restrict__ convw, const float* __restrict__ fc1w) {
    int gid = blockIdx.x * blockDim.x + threadIdx.x;
    bf h, l;
    split_bf(convw[gid], h, l);
    g_cw_hi[gid] = h; g_cw_lo[gid] = l;
    if (gid < CC*CC) {
        int j = gid >> 7, c = gid & 127;
        split_bf(fc1w[c*CC + j], h, l);
        g_w1t_hi[gid] = h; g_w1t_lo[gid] = l;
    }
}
__global__ void trans_split(const bf* __restrict__ hh, const bf* __restrict__ hl) {
    __shared__ uint32_t T[32][33];
    int n0 = blockIdx.x * 32;
    int cb = blockIdx.y & 3;
    int b = blockIdx.y >> 2;
    int c0 = cb * 32;
    int tx = threadIdx.x & 31, ty = threadIdx.x >> 5;
#pragma unroll
    for (int i = 0; i < 4; i++) {
        int c = c0 + ty + i * 8;
        size_t off = ((size_t)b * CC + c) * NN + n0 + tx;
        T[ty + i * 8][tx] = (uint32_t)__bfloat16_as_ushort(hh[off])
                          | ((uint32_t)__bfloat16_as_ushort(hl[off]) << 16);
    }
    __syncthreads();
#pragma unroll
    for (int i = 0; i < 4; i++) {
        int n = n0 + ty + i * 8;
        uint32_t v = T[tx][ty + i * 8];
        size_t o = ((size_t)b * NN + n) * CC + c0 + tx;
        g_nch[o] = __ushort_as_bfloat16((unsigned short)(v & 0xffff));
        g_ncl[o] = __ushort_as_bfloat16((unsigned short)(v >> 16));
    }
}

// ---------------- forward projection GEMM (bf16, spectral) ----------------
__global__ __launch_bounds__(256, 2) void gemm_fwd(const bf* __restrict__ Ahg,
                                                   const bf* __restrict__ Bhg,
                                                   float* __restrict__ outp) {
    __shared__ bf As[128*PAD], Bs[128*PAD];
    int split = blockIdx.x, b = blockIdx.y;
    int tid = threadIdx.x, w = tid >> 5, lane = tid & 31, g = lane >> 2, tg = lane & 3;
    int m0 = (w & 1) * 64, n0 = (w >> 1) * 32;
    const bf* As_g = Ahg + (size_t)b * CC * NN;
    const bf* Bs_g = Bhg + (size_t)b * KK * NN;
    float acc[4][4][4];
#pragma unroll
    for (int i = 0; i < 4; i++)
#pragma unroll
        for (int j = 0; j < 4; j++)
#pragma unroll
            for (int q = 0; q < 4; q++) acc[i][j][q] = 0.f;

    for (int ch = 0; ch < XS / 32; ch++) {
        int x0 = split * XS + ch * 32;
        cp_tile(As, As_g + x0, NN, tid);
        cp_tile(Bs, Bs_g + x0, NN, tid);
        __syncthreads();
        gemm_chunk1(As, Bs, acc, g, tg, m0, n0);
        __syncthreads();
    }
    float* pp = outp + (size_t)(split * BB + b) * CC * KK;
#pragma unroll
    for (int mt = 0; mt < 4; mt++) {
        int r0 = m0 + mt * 16 + g;
#pragma unroll
        for (int nt = 0; nt < 4; nt++) {
            int n = n0 + nt * 8 + tg * 2;
            *(float2*)&pp[r0 * KK + n] = make_float2(acc[mt][nt][0], acc[mt][nt][1]);
            *(float2*)&pp[(r0 + 8) * KK + n] = make_float2(acc[mt][nt][2], acc[mt][nt][3]);
        }
    }
}

// ---------------- fused inverse: spectral (bf16) + conv (split); writes hcn AND hnc ----------------
__global__ __launch_bounds__(256, 2) void inv3(const bf* __restrict__ hnc_hi, const bf* __restrict__ hnc_lo,
                                               bf* __restrict__ ohh, bf* __restrict__ ohl,
                                               bf* __restrict__ onch, bf* __restrict__ oncl,
                                               const float* __restrict__ convb,
                                               const float* __restrict__ mask,
                                               int l, int apply_gelu) {
    extern __shared__ char dyns[];
    bf* Ah = (bf*)dyns;
    bf* Al = Ah + 128 * PAD;
    bf* Bh = Al + 128 * PAD;
    bf* Bl = Bh + 128 * PAD;
    uint32_t* Tr = (uint32_t*)dyns;   // overlays tiles; used only after all MMA passes
    int xb = blockIdx.x * 128, b = blockIdx.y;
    int tid = threadIdx.x, w = tid >> 5, lane = tid & 31, g = lane >> 2, tg = lane & 3;
    int m0 = (w & 1) * 64, n0 = (w >> 1) * 32;
    float acc[4][4][4];
#pragma unroll
    for (int i = 0; i < 4; i++)
#pragma unroll
        for (int j = 0; j < 4; j++)
#pragma unroll
            for (int q = 0; q < 4; q++) acc[i][j][q] = 0.f;

    for (int pass = 0; pass < 2; pass++) {
        const bf* pA = (pass ? g_fsw : g_fcw) + (size_t)b*CC*KK;
        const bf* pB = (pass ? g_bs : g_bc) + ((size_t)b*NN + xb)*KK;
        for (int ch = 0; ch < 4; ch++) {
            int k0 = ch * 32;
            cp_tile(Ah, pA + k0, 128, tid);
            cp_tile(Bh, pB + k0, 128, tid);
            __syncthreads();
            gemm_chunk1(Ah, Bh, acc, g, tg, m0, n0);
            __syncthreads();
        }
    }
    {
        const bf* pAh = g_cw_hi + (size_t)l*CC*CC;
        const bf* pAl = g_cw_lo + (size_t)l*CC*CC;
        const bf* pBh = hnc_hi + ((size_t)b*NN + xb)*CC;
        const bf* pBl = hnc_lo + ((size_t)b*NN + xb)*CC;
        for (int ch = 0; ch < 4; ch++) {
            int k0 = ch * 32;
            cp_tile(Ah, pAh + k0, 128, tid);
            cp_tile(Al, pAl + k0, 128, tid);
            cp_tile(Bh, pBh + k0, 128, tid);
            cp_tile(Bl, pBl + k0, 128, tid);
            __syncthreads();
            gemm_chunk3(Ah, Al, Bh, Bl, acc, g, tg, m0, n0);
            __syncthreads();
        }
    }
#pragma unroll
    for (int mt = 0; mt < 4; mt++) {
        int r0 = m0 + mt * 16 + g, r1 = r0 + 8;
        float cb0 = convb[l * CC + r0], f00 = g_f0v[b * CC + r0];
        float cb1 = convb[l * CC + r1], f01 = g_f0v[b * CC + r1];
#pragma unroll
        for (int nt = 0; nt < 4; nt++) {
            int n = n0 + nt * 8 + tg * 2;
            float mk0 = mask[(size_t)b * NN + xb + n];
            float mk1 = mask[(size_t)b * NN + xb + n + 1];
            float v00 = acc[mt][nt][0] + cb0 + f00 * mk0;
            float v01 = acc[mt][nt][1] + cb0 + f00 * mk1;
            float v10 = acc[mt][nt][2] + cb1 + f01 * mk0;
            float v11 = acc[mt][nt][3] + cb1 + f01 * mk1;
            if (apply_gelu) {
                v00 = gelu_exact(v00); v01 = gelu_exact(v01);
                v10 = gelu_exact(v10); v11 = gelu_exact(v11);
            }
            bf h00, l00, h01, l01, h10, l10, h11, l11;
            split_bf(v00, h00, l00); split_bf(v01, h01, l01);
            split_bf(v10, h10, l10); split_bf(v11, h11, l11);
            uint32_t p00 = (uint32_t)__bfloat16_as_ushort(h00) | ((uint32_t)__bfloat16_as_ushort(l00) << 16);
            uint32_t p01 = (uint32_t)__bfloat16_as_ushort(h01) | ((uint32_t)__bfloat16_as_ushort(l01) << 16);
            uint32_t p10 = (uint32_t)__bfloat16_as_ushort(h10) | ((uint32_t)__bfloat16_as_ushort(l10) << 16);
            uint32_t p11 = (uint32_t)__bfloat16_as_ushort(h11) | ((uint32_t)__bfloat16_as_ushort(l11) << 16);
            if (apply_gelu) {   // hcn consumed only by next layer; last layer skips
                size_t o0 = ((size_t)b * CC + r0) * NN + xb + n;
                size_t o1 = ((size_t)b * CC + r1) * NN + xb + n;
                *(uint32_t*)(ohh + o0) = (uint32_t)__bfloat16_as_ushort(h00) | ((uint32_t)__bfloat16_as_ushort(h01) << 16);
                *(uint32_t*)(ohl + o0) = (uint32_t)__bfloat16_as_ushort(l00) | ((uint32_t)__bfloat16_as_ushort(l01) << 16);
                *(uint32_t*)(ohh + o1) = (uint32_t)__bfloat16_as_ushort(h10) | ((uint32_t)__bfloat16_as_ushort(h11) << 16);
                *(uint32_t*)(ohl + o1) = (uint32_t)__bfloat16_as_ushort(l10) | ((uint32_t)__bfloat16_as_ushort(l11) << 16);
            }
            Tr[n * TRS + r0]       = p00;
            Tr[(n + 1) * TRS + r0] = p01;
            Tr[n * TRS + r1]       = p10;
            Tr[(n + 1) * TRS + r1] = p11;
        }
    }
    __syncthreads();
    {
        int xq = tid >> 1;
        int c0t = (tid & 1) * 64;
        size_t ob = ((size_t)b * NN + xb + xq) * CC + c0t;
#pragma unroll
        for (int q = 0; q < 8; q++) {
            __align__(16) unsigned short hh8[8], ll8[8];
#pragma unroll
            for (int c = 0; c < 8; c++) {
                uint32_t v = Tr[xq * TRS + c0t + q * 8 + c];
                hh8[c] = (unsigned short)(v & 0xffff);
                ll8[c] = (unsigned short)(v >> 16);
            }
            *(uint4*)(onch + ob + q * 8) = *(uint4*)hh8;
            *(uint4*)(oncl + ob + q * 8) = *(uint4*)ll8;
        }
    }
}

// ---------------- small kernels ----------------
__global__ void reduce_kernel() {
    int gid = (blockIdx.x * blockDim.x + threadIdx.x) * 4;
    float4 sc = make_float4(0.f, 0.f, 0.f, 0.f);
    float4 ss = make_float4(0.f, 0.f, 0.f, 0.f);
#pragma unroll
    for (int s = 0; s < NSPLIT; s++) {
        float4 a = *(const float4*)&g_pc[(size_t)s * BB * CC * KK + gid];
        float4 c = *(const float4*)&g_ps[(size_t)s * BB * CC * KK + gid];
        sc.x += a.x; sc.y += a.y; sc.z += a.z; sc.w += a.w;
        ss.x += c.x; ss.y += c.y; ss.z += c.z; ss.w += c.w;
    }
    *(float4*)&g_xc[gid] = sc;
    *(float4*)&g_xs[gid] = make_float4(-ss.x, -ss.y, -ss.z, -ss.w);
}
__global__ void x0_kernel(const bf* __restrict__ hh,
                          const float* __restrict__ nw, const float* __restrict__ mask) {
    int i = blockIdx.x, b = blockIdx.y;
    const bf* rh = hh + ((size_t)b * CC + i) * NN;
    const float* nwb = nw + b * NN;
    const float* mb = mask + b * NN;
    float acc = 0.f;
    for (int x = threadIdx.x; x < NN; x += 256)
        acc += __bfloat162float(rh[x]) * nwb[x] * mb[x];
    __shared__ float red[256];
    red[threadIdx.x] = acc;
    __syncthreads();
    for (int s = 128; s > 0; s >>= 1) {
        if (threadIdx.x < s) red[threadIdx.x] += red[threadIdx.x + s];
        __syncthreads();
    }
    if (threadIdx.x == 0) g_x0v[b * CC + i] = red[0];
}
__global__ void f0_kernel(const float* __restrict__ w0, int l) {
    int b = blockIdx.x, o = threadIdx.x;
    __shared__ float xs[CC];
    xs[o] = g_x0v[b * CC + o];
    __syncthreads();
    const float* w = w0 + (size_t)l * CC * CC;
    float acc = 0.f;
#pragma unroll 8
    for (int i = 0; i < CC; i++) acc += xs[i] * w[i * CC + o];
    g_f0v[b * CC + o] = acc;
}
__global__ void mix_kernel(const float* __restrict__ wc, const float* __restrict__ ws, int l) {
    int o = blockIdx.x, b = blockIdx.y, k = threadIdx.x;
    const float* wcl = wc + (size_t)l * CC * CC * KK;
    const float* wsl = ws + (size_t)l * CC * CC * KK;
    float fcA = 0.f, fsA = 0.f;
#pragma unroll 4
    for (int i = 0; i < CC; i++) {
        float xc = g_xc[(b * CC + i) * KK + k];
        float xv = g_xs[(b * CC + i) * KK + k];
        float wcv = wcl[((size_t)i * CC + o) * KK + k];
        float wsv = wsl[((size_t)i * CC + o) * KK + k];
        fcA += xc * wcv - xv * wsv;
        fsA += xv * wcv + xc * wsv;
    }
    int idx = (b * CC + o) * KK + k;
    g_fcw[idx] = __float2bfloat16(2.0f * fcA);
    g_fsw[idx] = __float2bfloat16(-2.0f * fsA);
}

// ---------------- fused fc1 (MMA split) + fc2 + mask ----------------
__global__ __launch_bounds__(256, 2) void fc1fc2(const bf* __restrict__ hnc_hi, const bf* __restrict__ hnc_lo,
                                                 const float* __restrict__ b1,
                                                 const float* __restrict__ w2,
                                                 const float* __restrict__ b2,
                                                 const float* __restrict__ mask,
                                                 float* __restrict__ out) {
    extern __shared__ char dyns[];
    bf* Ah = (bf*)dyns;
    bf* Al = Ah + 128 * PAD;
    bf* Bh = Al + 128 * PAD;
    bf* Bl = Bh + 128 * PAD;
    float* Tsm = (float*)dyns;
    float* w2s = (float*)(dyns + 128 * TRS * 4);
    float* part = w2s + 128;
    int xb = blockIdx.x * 128, b = blockIdx.y;
    int tid = threadIdx.x, w = tid >> 5, lane = tid & 31, g = lane >> 2, tg = lane & 3;
    int m0 = (w & 1) * 64, n0 = (w >> 1) * 32;
    if (tid < 128) w2s[tid] = w2[tid];
    const bf* pBh = hnc_hi + ((size_t)b * NN + xb) * CC;
    const bf* pBl = hnc_lo + ((size_t)b * NN + xb) * CC;
    float acc[4][4][4];
#pragma unroll
    for (int i = 0; i < 4; i++)
#pragma unroll
        for (int j = 0; j < 4; j++)
#pragma unroll
            for (int q = 0; q < 4; q++) acc[i][j][q] = 0.f;

    for (int ch = 0; ch < 4; ch++) {
        int k0 = ch * 32;
        cp_tile(Ah, g_w1t_hi + k0, 128, tid);
        cp_tile(Al, g_w1t_lo + k0, 128, tid);
        cp_tile(Bh, pBh + k0, 128, tid);
        cp_tile(Bl, pBl + k0, 128, tid);
        __syncthreads();
        gemm_chunk3(Ah, Al, Bh, Bl, acc, g, tg, m0, n0);
        __syncthreads();
    }
#pragma unroll
    for (int mt = 0; mt < 4; mt++) {
        int r0 = m0 + mt * 16 + g, r1 = r0 + 8;
        float bb0 = b1[r0], bb8 = b1[r1];
#pragma unroll
        for (int nt = 0; nt < 4; nt++) {
            int n = n0 + nt * 8 + tg * 2;
            Tsm[n * TRS + r0]       = gelu_exact(acc[mt][nt][0] + bb0);
            Tsm[(n + 1) * TRS + r0] = gelu_exact(acc[mt][nt][1] + bb0);
            Tsm[n * TRS + r1]       = gelu_exact(acc[mt][nt][2] + bb8);
            Tsm[(n + 1) * TRS + r1] = gelu_exact(acc[mt][nt][3] + bb8);
        }
    }
    __syncthreads();
    {
        int xq = tid >> 1;
        int jh = (tid & 1) * 64;
        float p = 0.f;
#pragma unroll 8
        for (int j = 0; j < 64; j++)
            p += Tsm[xq * TRS + jh + j] * w2s[jh + j];
        part[tid] = p;
        __syncthreads();
        if ((tid & 1) == 0) {
            size_t xi = (size_t)b * NN + xb + xq;
            out[xi] = (part[tid] + part[tid + 1] + b2[0]) * mask[xi];
        }
    }
}

// ---------------- launch ----------------
extern "C" void kernel_launch(void* const* d_in, const int* in_sizes, int n_in,
                              void* d_out, int out_size) {
    const float* x     = (const float*)d_in[0];
    const float* nodes = (const float*)d_in[1];
    const float* mask  = (const float*)d_in[2];
    const float* nw    = (const float*)d_in[3];
    const float* modes = (const float*)d_in[4];
    const float* fc0w  = (const float*)d_in[5];
    const float* fc0b  = (const float*)d_in[6];
    const float* wc    = (const float*)d_in[7];
    const float* ws_   = (const float*)d_in[8];
    const float* w0    = (const float*)d_in[9];
    const float* convw = (const float*)d_in[10];
    const float* convb = (const float*)d_in[11];
    const float* fc1w  = (const float*)d_in[12];
    const float* fc1b  = (const float*)d_in[13];
    const float* fc2w  = (const float*)d_in[14];
    const float* fc2b  = (const float*)d_in[15];
    float* out = (float*)d_out;

    const int INV_SMEM = 128 * TRS * 4;                    // 67584
    const int FC_SMEM  = 128 * TRS * 4 + (128 + 256) * 4;  // 69120
    cudaFuncSetAttribute(inv3, cudaFuncAttributeMaxDynamicSharedMemorySize, INV_SMEM);
    cudaFuncSetAttribute(fc1fc2, cudaFuncAttributeMaxDynamicSharedMemorySize, FC_SMEM);

    float *pcp, *psp;
    bf *wbcp, *wbsp, *nch, *ncl, *hh0, *hl0;
    cudaGetSymbolAddress((void**)&pcp, g_pc);
    cudaGetSymbolAddress((void**)&psp, g_ps);
    cudaGetSymbolAddress((void**)&wbcp, g_wbc);
    cudaGetSymbolAddress((void**)&wbsp, g_wbs);
    cudaGetSymbolAddress((void**)&nch, g_nch);
    cudaGetSymbolAddress((void**)&ncl, g_ncl);
    cudaGetSymbolAddress((void**)&hh0, g_hcnh);
    cudaGetSymbolAddress((void**)&hl0, g_hcnl);
    bf* hh1 = hh0 + (size_t)BB*CC*NN;
    bf* hl1 = hl0 + (size_t)BB*CC*NN;

    bases_all<<<dim3(NN/32, BB), 256>>>(nodes, mask, nw, modes);
    fc0_kernel<<<(BB*CC*NN)/256, 256>>>(x, fc0w, fc0b, hh0, hl0);
    split_weights_kernel<<<(LL*CC*CC)/256, 256>>>(convw, fc1w);
    trans_split<<<dim3(NN/32, 4*BB), 256>>>(hh0, hl0);

    bf *ch = hh0, *cl = hl0, *oh = hh1, *ol = hl1;
    for (int l = 0; l < LL; l++) {
        gemm_fwd<<<dim3(NSPLIT, BB), 256>>>(ch, wbcp, pcp);
        gemm_fwd<<<dim3(NSPLIT, BB), 256>>>(ch, wbsp, psp);
        reduce_kernel<<<(BB*CC*KK)/1024, 256>>>();
        x0_kernel<<<dim3(CC, BB), 256>>>(ch, nw, mask);
        f0_kernel<<<BB, CC>>>(w0, l);
        mix_kernel<<<dim3(CC, BB), KK>>>(wc, ws_, l);
        inv3<<<dim3(NN/128, BB), 256, INV_SMEM>>>(nch, ncl, oh, ol, nch, ncl,
                                                  convb, mask, l, (l != LL-1) ? 1 : 0);
        bf* t;
        t = ch; ch = oh; oh = t;
        t = cl; cl = ol; ol = t;
    }
    fc1fc2<<<dim3(NN/128, BB), 256, FC_SMEM>>>(nch, ncl, fc1b, fc2w, fc2b, mask, out);
}

// round 13
// speedup vs baseline: 1.1771x; 1.0048x over previous
#include <cuda_runtime.h>
#include <cuda_bf16.h>
#include <cstdint>
#include <math.h>

#define BB 8
#define NN 16384
#define KK 128
#define CC 128
#define LL 4
#define NSPLIT 32
#define XS (NN / NSPLIT)   // 512
#define PAD 40
#define TSZ (128 * PAD)
#define TRS 132

typedef __nv_bfloat16 bf;

// ---------------- device scratch ----------------
__device__ bf g_bc[BB*NN*KK];
__device__ bf g_bs[BB*NN*KK];
__device__ bf g_wbc[BB*KK*NN];
__device__ bf g_wbs[BB*KK*NN];
__device__ bf g_hcnh[2][BB*CC*NN], g_hcnl[2][BB*CC*NN];
__device__ bf g_nch[BB*NN*CC], g_ncl[BB*NN*CC];
__device__ bf g_pc[NSPLIT*BB*CC*KK], g_ps[NSPLIT*BB*CC*KK];   // bf16 partials
__device__ float g_xc[BB*CC*KK], g_xs[BB*CC*KK];
__device__ float g_x0v[BB*CC], g_f0v[BB*CC];
__device__ bf g_fcw[BB*CC*KK];
__device__ bf g_fsw[BB*CC*KK];
__device__ bf g_cw_hi[LL*CC*CC], g_cw_lo[LL*CC*CC];
__device__ bf g_w1t_hi[CC*CC], g_w1t_lo[CC*CC];

// ---------------- helpers ----------------
__device__ __forceinline__ void split_bf(float v, bf& h, bf& l) {
    h = __float2bfloat16(v);
    l = __float2bfloat16(v - __bfloat162float(h));
}
__device__ __forceinline__ float gelu_exact(float v) {
    return 0.5f * v * (1.0f + erff(v * 0.70710678118654752f));
}
#define MMA(d, a0, a1, a2, a3, b0, b1) \
    asm volatile("mma.sync.aligned.m16n8k16.row.col.f32.bf16.bf16.f32 " \
        "{%0,%1,%2,%3}, {%4,%5,%6,%7}, {%8,%9}, {%0,%1,%2,%3};" \
        : "+f"((d)[0]), "+f"((d)[1]), "+f"((d)[2]), "+f"((d)[3]) \
        : "r"(a0), "r"(a1), "r"(a2), "r"(a3), "r"(b0), "r"(b1))

__device__ __forceinline__ void cp_tile(bf* dst, const bf* __restrict__ src, size_t ldm, int tid) {
#pragma unroll
    for (int j = 0; j < 2; j++) {
        int idx = tid + j * 256;
        int row = idx >> 2, q = idx & 3;
        *(uint4*)(dst + row * PAD + q * 8) = *(const uint4*)(src + (size_t)row * ldm + q * 8);
    }
}

__device__ __forceinline__ void gemm_chunk1(const bf* A, const bf* B,
                                            float acc[4][4][4], int g, int tg, int m0, int n0) {
#pragma unroll
    for (int ks = 0; ks < 32; ks += 16) {
        uint32_t bh[4][2];
#pragma unroll
        for (int nt = 0; nt < 4; nt++) {
            const bf* p = B + (n0 + nt * 8 + g) * PAD + ks + tg * 2;
            bh[nt][0] = *(const uint32_t*)p;
            bh[nt][1] = *(const uint32_t*)(p + 8);
        }
#pragma unroll
        for (int mt = 0; mt < 4; mt++) {
            const bf* p = A + (m0 + mt * 16 + g) * PAD + ks + tg * 2;
            uint32_t a0 = *(const uint32_t*)p;
            uint32_t a1 = *(const uint32_t*)(p + 8 * PAD);
            uint32_t a2 = *(const uint32_t*)(p + 8);
            uint32_t a3 = *(const uint32_t*)(p + 8 * PAD + 8);
#pragma unroll
            for (int nt = 0; nt < 4; nt++)
                MMA(acc[mt][nt], a0, a1, a2, a3, bh[nt][0], bh[nt][1]);
        }
    }
}

__device__ __forceinline__ void gemm_chunk3(const bf* Ah, const bf* Al, const bf* Bh, const bf* Bl,
                                            float acc[4][4][4], int g, int tg, int m0, int n0) {
#pragma unroll
    for (int ks = 0; ks < 32; ks += 16) {
        uint32_t bh[4][2], bl[4][2];
#pragma unroll
        for (int nt = 0; nt < 4; nt++) {
            const bf* p = Bh + (n0 + nt * 8 + g) * PAD + ks + tg * 2;
            bh[nt][0] = *(const uint32_t*)p;
            bh[nt][1] = *(const uint32_t*)(p + 8);
            const bf* q = Bl + (n0 + nt * 8 + g) * PAD + ks + tg * 2;
            bl[nt][0] = *(const uint32_t*)q;
            bl[nt][1] = *(const uint32_t*)(q + 8);
        }
#pragma unroll
        for (int mt = 0; mt < 4; mt++) {
            const bf* p = Ah + (m0 + mt * 16 + g) * PAD + ks + tg * 2;
            uint32_t ah0 = *(const uint32_t*)p;
            uint32_t ah1 = *(const uint32_t*)(p + 8 * PAD);
            uint32_t ah2 = *(const uint32_t*)(p + 8);
            uint32_t ah3 = *(const uint32_t*)(p + 8 * PAD + 8);
            const bf* q = Al + (m0 + mt * 16 + g) * PAD + ks + tg * 2;
            uint32_t al0 = *(const uint32_t*)q;
            uint32_t al1 = *(const uint32_t*)(q + 8 * PAD);
            uint32_t al2 = *(const uint32_t*)(q + 8);
            uint32_t al3 = *(const uint32_t*)(q + 8 * PAD + 8);
#pragma unroll
            for (int nt = 0; nt < 4; nt++) {
                MMA(acc[mt][nt], ah0, ah1, ah2, ah3, bh[nt][0], bh[nt][1]);
                MMA(acc[mt][nt], ah0, ah1, ah2, ah3, bl[nt][0], bl[nt][1]);
                MMA(acc[mt][nt], al0, al1, al2, al3, bh[nt][0], bh[nt][1]);
            }
        }
    }
}

// ---------------- merged bases producer ----------------
__global__ void bases_all(const float* __restrict__ nodes, const float* __restrict__ mask,
                          const float* __restrict__ nw, const float* __restrict__ modes) {
    __shared__ unsigned short Tc[KK*32], Tsn[KK*32];
    int n0 = blockIdx.x * 32, b = blockIdx.y, tid = threadIdx.x;
    for (int idx = tid; idx < 32 * KK; idx += 256) {
        int n = idx >> 7, k = idx & 127;
        int bn = b * NN + n0 + n;
        float m = mask[bn];
        float wgt = m * nw[bn];
        float t = nodes[bn*2] * __ldg(&modes[k*2]) + nodes[bn*2+1] * __ldg(&modes[k*2+1]);
        float s, c; sincosf(t, &s, &c);
        size_t o = (size_t)bn * KK + k;
        g_bc[o] = __float2bfloat16(c * m);
        g_bs[o] = __float2bfloat16(s * m);
        Tc[k * 32 + n]  = __bfloat16_as_ushort(__float2bfloat16(c * wgt));
        Tsn[k * 32 + n] = __bfloat16_as_ushort(__float2bfloat16(s * wgt));
    }
    __syncthreads();
    for (int idx = tid; idx < KK * 32; idx += 256) {
        int n = idx & 31, k = idx >> 5;
        size_t o = ((size_t)(b * KK + k)) * NN + n0 + n;
        g_wbc[o] = __ushort_as_bfloat16(Tc[k * 32 + n]);
        g_wbs[o] = __ushort_as_bfloat16(Tsn[k * 32 + n]);
    }
}
__global__ void fc0_kernel(const float* __restrict__ x, const float* __restrict__ w,
                           const float* __restrict__ bias,
                           bf* __restrict__ ohh, bf* __restrict__ ohl) {
    int gid = blockIdx.x * blockDim.x + threadIdx.x;
    int n = gid & (NN-1), c = (gid >> 14) & (CC-1), b = gid >> 21;
    const float* xp = x + ((size_t)b*NN + n)*3;
    float v = bias[c] + xp[0]*w[c] + xp[1]*w[CC+c] + xp[2]*w[2*CC+c];
    bf hi, lo; split_bf(v, hi, lo);
    ohh[gid] = hi; ohl[gid] = lo;
}
__global__ void split_weights_kernel(const float* __restrict__ convw, const float* __restrict__ fc1w) {
    int gid = blockIdx.x * blockDim.x + threadIdx.x;
    bf h, l;
    split_bf(convw[gid], h, l);
    g_cw_hi[gid] = h; g_cw_lo[gid] = l;
    if (gid < CC*CC) {
        int j = gid >> 7, c = gid & 127;
        split_bf(fc1w[c*CC + j], h, l);
        g_w1t_hi[gid] = h; g_w1t_lo[gid] = l;
    }
}
__global__ void trans_split(const bf* __restrict__ hh, const bf* __restrict__ hl) {
    __shared__ uint32_t T[32][33];
    int n0 = blockIdx.x * 32;
    int cb = blockIdx.y & 3;
    int b = blockIdx.y >> 2;
    int c0 = cb * 32;
    int tx = threadIdx.x & 31, ty = threadIdx.x >> 5;
#pragma unroll
    for (int i = 0; i < 4; i++) {
        int c = c0 + ty + i * 8;
        size_t off = ((size_t)b * CC + c) * NN + n0 + tx;
        T[ty + i * 8][tx] = (uint32_t)__bfloat16_as_ushort(hh[off])
                          | ((uint32_t)__bfloat16_as_ushort(hl[off]) << 16);
    }
    __syncthreads();
#pragma unroll
    for (int i = 0; i < 4; i++) {
        int n = n0 + ty + i * 8;
        uint32_t v = T[tx][ty + i * 8];
        size_t o = ((size_t)b * NN + n) * CC + c0 + tx;
        g_nch[o] = __ushort_as_bfloat16((unsigned short)(v & 0xffff));
        g_ncl[o] = __ushort_as_bfloat16((unsigned short)(v >> 16));
    }
}

// ---------------- forward projection GEMM (bf16, double-buffered, bf16 partials) ----------------
__global__ __launch_bounds__(256, 2) void gemm_fwd(const bf* __restrict__ Ahg,
                                                   const bf* __restrict__ Bhg,
                                                   bf* __restrict__ outp) {
    __shared__ bf As[2][TSZ], Bs[2][TSZ];
    int split = blockIdx.x, b = blockIdx.y;
    int tid = threadIdx.x, w = tid >> 5, lane = tid & 31, g = lane >> 2, tg = lane & 3;
    int m0 = (w & 1) * 64, n0 = (w >> 1) * 32;
    const bf* As_g = Ahg + (size_t)b * CC * NN + (size_t)split * XS;
    const bf* Bs_g = Bhg + (size_t)b * KK * NN + (size_t)split * XS;
    float acc[4][4][4];
#pragma unroll
    for (int i = 0; i < 4; i++)
#pragma unroll
        for (int j = 0; j < 4; j++)
#pragma unroll
            for (int q = 0; q < 4; q++) acc[i][j][q] = 0.f;

    const int NCH = XS / 32;   // 16
    cp_tile(As[0], As_g, NN, tid);
    cp_tile(Bs[0], Bs_g, NN, tid);
    __syncthreads();
    for (int ch = 0; ch < NCH; ch++) {
        int cur = ch & 1;
        if (ch + 1 < NCH) {
            cp_tile(As[cur ^ 1], As_g + (ch + 1) * 32, NN, tid);
            cp_tile(Bs[cur ^ 1], Bs_g + (ch + 1) * 32, NN, tid);
        }
        gemm_chunk1(As[cur], Bs[cur], acc, g, tg, m0, n0);
        __syncthreads();
    }
    bf* pp = outp + (size_t)(split * BB + b) * CC * KK;
#pragma unroll
    for (int mt = 0; mt < 4; mt++) {
        int r0 = m0 + mt * 16 + g;
#pragma unroll
        for (int nt = 0; nt < 4; nt++) {
            int n = n0 + nt * 8 + tg * 2;
            uint32_t v0 = (uint32_t)__bfloat16_as_ushort(__float2bfloat16(acc[mt][nt][0]))
                        | ((uint32_t)__bfloat16_as_ushort(__float2bfloat16(acc[mt][nt][1])) << 16);
            uint32_t v1 = (uint32_t)__bfloat16_as_ushort(__float2bfloat16(acc[mt][nt][2]))
                        | ((uint32_t)__bfloat16_as_ushort(__float2bfloat16(acc[mt][nt][3])) << 16);
            *(uint32_t*)(pp + r0 * KK + n) = v0;
            *(uint32_t*)(pp + (r0 + 8) * KK + n) = v1;
        }
    }
}

// ---------------- fused inverse: spectral (bf16) + conv (split); writes hcn AND hnc ----------------
__global__ __launch_bounds__(256, 2) void inv3(const bf* __restrict__ hnc_hi, const bf* __restrict__ hnc_lo,
                                               bf* __restrict__ ohh, bf* __restrict__ ohl,
                                               bf* __restrict__ onch, bf* __restrict__ oncl,
                                               const float* __restrict__ convb,
                                               const float* __restrict__ mask,
                                               int l, int apply_gelu) {
    extern __shared__ char dyns[];
    bf* Ah = (bf*)dyns;
    bf* Al = Ah + TSZ;
    bf* Bh = Al + TSZ;
    bf* Bl = Bh + TSZ;
    uint32_t* Tr = (uint32_t*)dyns;
    int xb = blockIdx.x * 128, b = blockIdx.y;
    int tid = threadIdx.x, w = tid >> 5, lane = tid & 31, g = lane >> 2, tg = lane & 3;
    int m0 = (w & 1) * 64, n0 = (w >> 1) * 32;
    float acc[4][4][4];
#pragma unroll
    for (int i = 0; i < 4; i++)
#pragma unroll
        for (int j = 0; j < 4; j++)
#pragma unroll
            for (int q = 0; q < 4; q++) acc[i][j][q] = 0.f;

    for (int pass = 0; pass < 2; pass++) {
        const bf* pA = (pass ? g_fsw : g_fcw) + (size_t)b*CC*KK;
        const bf* pB = (pass ? g_bs : g_bc) + ((size_t)b*NN + xb)*KK;
        for (int ch = 0; ch < 4; ch++) {
            int k0 = ch * 32;
            cp_tile(Ah, pA + k0, 128, tid);
            cp_tile(Bh, pB + k0, 128, tid);
            __syncthreads();
            gemm_chunk1(Ah, Bh, acc, g, tg, m0, n0);
            __syncthreads();
        }
    }
    {
        const bf* pAh = g_cw_hi + (size_t)l*CC*CC;
        const bf* pAl = g_cw_lo + (size_t)l*CC*CC;
        const bf* pBh = hnc_hi + ((size_t)b*NN + xb)*CC;
        const bf* pBl = hnc_lo + ((size_t)b*NN + xb)*CC;
        for (int ch = 0; ch < 4; ch++) {
            int k0 = ch * 32;
            cp_tile(Ah, pAh + k0, 128, tid);
            cp_tile(Al, pAl + k0, 128, tid);
            cp_tile(Bh, pBh + k0, 128, tid);
            cp_tile(Bl, pBl + k0, 128, tid);
            __syncthreads();
            gemm_chunk3(Ah, Al, Bh, Bl, acc, g, tg, m0, n0);
            __syncthreads();
        }
    }
#pragma unroll
    for (int mt = 0; mt < 4; mt++) {
        int r0 = m0 + mt * 16 + g, r1 = r0 + 8;
        float cb0 = convb[l * CC + r0], f00 = g_f0v[b * CC + r0];
        float cb1 = convb[l * CC + r1], f01 = g_f0v[b * CC + r1];
#pragma unroll
        for (int nt = 0; nt < 4; nt++) {
            int n = n0 + nt * 8 + tg * 2;
            float mk0 = mask[(size_t)b * NN + xb + n];
            float mk1 = mask[(size_t)b * NN + xb + n + 1];
            float v00 = acc[mt][nt][0] + cb0 + f00 * mk0;
            float v01 = acc[mt][nt][1] + cb0 + f00 * mk1;
            float v10 = acc[mt][nt][2] + cb1 + f01 * mk0;
            float v11 = acc[mt][nt][3] + cb1 + f01 * mk1;
            if (apply_gelu) {
                v00 = gelu_exact(v00); v01 = gelu_exact(v01);
                v10 = gelu_exact(v10); v11 = gelu_exact(v11);
            }
            bf h00, l00, h01, l01, h10, l10, h11, l11;
            split_bf(v00, h00, l00); split_bf(v01, h01, l01);
            split_bf(v10, h10, l10); split_bf(v11, h11, l11);
            uint32_t p00 = (uint32_t)__bfloat16_as_ushort(h00) | ((uint32_t)__bfloat16_as_ushort(l00) << 16);
            uint32_t p01 = (uint32_t)__bfloat16_as_ushort(h01) | ((uint32_t)__bfloat16_as_ushort(l01) << 16);
            uint32_t p10 = (uint32_t)__bfloat16_as_ushort(h10) | ((uint32_t)__bfloat16_as_ushort(l10) << 16);
            uint32_t p11 = (uint32_t)__bfloat16_as_ushort(h11) | ((uint32_t)__bfloat16_as_ushort(l11) << 16);
            if (apply_gelu) {
                size_t o0 = ((size_t)b * CC + r0) * NN + xb + n;
                size_t o1 = ((size_t)b * CC + r1) * NN + xb + n;
                *(uint32_t*)(ohh + o0) = (uint32_t)__bfloat16_as_ushort(h00) | ((uint32_t)__bfloat16_as_ushort(h01) << 16);
                *(uint32_t*)(ohl + o0) = (uint32_t)__bfloat16_as_ushort(l00) | ((uint32_t)__bfloat16_as_ushort(l01) << 16);
                *(uint32_t*)(ohh + o1) = (uint32_t)__bfloat16_as_ushort(h10) | ((uint32_t)__bfloat16_as_ushort(h11) << 16);
                *(uint32_t*)(ohl + o1) = (uint32_t)__bfloat16_as_ushort(l10) | ((uint32_t)__bfloat16_as_ushort(l11) << 16);
            }
            Tr[n * TRS + r0]       = p00;
            Tr[(n + 1) * TRS + r0] = p01;
            Tr[n * TRS + r1]       = p10;
            Tr[(n + 1) * TRS + r1] = p11;
        }
    }
    __syncthreads();
    {
        int xq = tid >> 1;
        int c0t = (tid & 1) * 64;
        size_t ob = ((size_t)b * NN + xb + xq) * CC + c0t;
#pragma unroll
        for (int q = 0; q < 8; q++) {
            __align__(16) unsigned short hh8[8], ll8[8];
#pragma unroll
            for (int c = 0; c < 8; c++) {
                uint32_t v = Tr[xq * TRS + c0t + q * 8 + c];
                hh8[c] = (unsigned short)(v & 0xffff);
                ll8[c] = (unsigned short)(v >> 16);
            }
            *(uint4*)(onch + ob + q * 8) = *(uint4*)hh8;
            *(uint4*)(oncl + ob + q * 8) = *(uint4*)ll8;
        }
    }
}

// ---------------- small kernels ----------------
__global__ void reduce_kernel() {
    int gid = (blockIdx.x * blockDim.x + threadIdx.x) * 8;   // 8 bf16 per thread
    float sc[8], ss[8];
#pragma unroll
    for (int q = 0; q < 8; q++) { sc[q] = 0.f; ss[q] = 0.f; }
#pragma unroll
    for (int s = 0; s < NSPLIT; s++) {
        uint4 a = *(const uint4*)&g_pc[(size_t)s * BB * CC * KK + gid];
        uint4 c = *(const uint4*)&g_ps[(size_t)s * BB * CC * KK + gid];
        const uint32_t* ap = (const uint32_t*)&a;
        const uint32_t* cp = (const uint32_t*)&c;
#pragma unroll
        for (int q = 0; q < 4; q++) {
            sc[q*2]   += __bfloat162float(__ushort_as_bfloat16((unsigned short)(ap[q] & 0xffff)));
            sc[q*2+1] += __bfloat162float(__ushort_as_bfloat16((unsigned short)(ap[q] >> 16)));
            ss[q*2]   += __bfloat162float(__ushort_as_bfloat16((unsigned short)(cp[q] & 0xffff)));
            ss[q*2+1] += __bfloat162float(__ushort_as_bfloat16((unsigned short)(cp[q] >> 16)));
        }
    }
#pragma unroll
    for (int q = 0; q < 8; q += 4) {
        *(float4*)&g_xc[gid + q] = make_float4(sc[q], sc[q+1], sc[q+2], sc[q+3]);
        *(float4*)&g_xs[gid + q] = make_float4(-ss[q], -ss[q+1], -ss[q+2], -ss[q+3]);
    }
}
__global__ void x0_kernel(const bf* __restrict__ hh,
                          const float* __restrict__ nw, const float* __restrict__ mask) {
    int i = blockIdx.x, b = blockIdx.y;
    const bf* rh = hh + ((size_t)b * CC + i) * NN;
    const float* nwb = nw + b * NN;
    const float* mb = mask + b * NN;
    float acc = 0.f;
    for (int x = threadIdx.x; x < NN; x += 256)
        acc += __bfloat162float(rh[x]) * nwb[x] * mb[x];
    __shared__ float red[256];
    red[threadIdx.x] = acc;
    __syncthreads();
    for (int s = 128; s > 0; s >>= 1) {
        if (threadIdx.x < s) red[threadIdx.x] += red[threadIdx.x + s];
        __syncthreads();
    }
    if (threadIdx.x == 0) g_x0v[b * CC + i] = red[0];
}
__global__ void f0_kernel(const float* __restrict__ w0, int l) {
    int b = blockIdx.x, o = threadIdx.x;
    __shared__ float xs[CC];
    xs[o] = g_x0v[b * CC + o];
    __syncthreads();
    const float* w = w0 + (size_t)l * CC * CC;
    float acc = 0.f;
#pragma unroll 8
    for (int i = 0; i < CC; i++) acc += xs[i] * w[i * CC + o];
    g_f0v[b * CC + o] = acc;
}
__global__ void mix_kernel(const float* __restrict__ wc, const float* __restrict__ ws, int l) {
    int o = blockIdx.x, b = blockIdx.y, k = threadIdx.x;
    const float* wcl = wc + (size_t)l * CC * CC * KK;
    const float* wsl = ws + (size_t)l * CC * CC * KK;
    float fcA = 0.f, fsA = 0.f;
#pragma unroll 4
    for (int i = 0; i < CC; i++) {
        float xc = g_xc[(b * CC + i) * KK + k];
        float xv = g_xs[(b * CC + i) * KK + k];
        float wcv = wcl[((size_t)i * CC + o) * KK + k];
        float wsv = wsl[((size_t)i * CC + o) * KK + k];
        fcA += xc * wcv - xv * wsv;
        fsA += xv * wcv + xc * wsv;
    }
    int idx = (b * CC + o) * KK + k;
    g_fcw[idx] = __float2bfloat16(2.0f * fcA);
    g_fsw[idx] = __float2bfloat16(-2.0f * fsA);
}

// ---------------- fused fc1 (MMA split) + fc2 + mask ----------------
__global__ __launch_bounds__(256, 2) void fc1fc2(const bf* __restrict__ hnc_hi, const bf* __restrict__ hnc_lo,
                                                 const float* __restrict__ b1,
                                                 const float* __restrict__ w2,
                                                 const float* __restrict__ b2,
                                                 const float* __restrict__ mask,
                                                 float* __restrict__ out) {
    extern __shared__ char dyns[];
    bf* Ah = (bf*)dyns;
    bf* Al = Ah + TSZ;
    bf* Bh = Al + TSZ;
    bf* Bl = Bh + TSZ;
    float* Tsm = (float*)dyns;
    float* w2s = (float*)(dyns + 128 * TRS * 4);
    float* part = w2s + 128;
    int xb = blockIdx.x * 128, b = blockIdx.y;
    int tid = threadIdx.x, w = tid >> 5, lane = tid & 31, g = lane >> 2, tg = lane & 3;
    int m0 = (w & 1) * 64, n0 = (w >> 1) * 32;
    if (tid < 128) w2s[tid] = w2[tid];
    const bf* pBh = hnc_hi + ((size_t)b * NN + xb) * CC;
    const bf* pBl = hnc_lo + ((size_t)b * NN + xb) * CC;
    float acc[4][4][4];
#pragma unroll
    for (int i = 0; i < 4; i++)
#pragma unroll
        for (int j = 0; j < 4; j++)
#pragma unroll
            for (int q = 0; q < 4; q++) acc[i][j][q] = 0.f;

    for (int ch = 0; ch < 4; ch++) {
        int k0 = ch * 32;
        cp_tile(Ah, g_w1t_hi + k0, 128, tid);
        cp_tile(Al, g_w1t_lo + k0, 128, tid);
        cp_tile(Bh, pBh + k0, 128, tid);
        cp_tile(Bl, pBl + k0, 128, tid);
        __syncthreads();
        gemm_chunk3(Ah, Al, Bh, Bl, acc, g, tg, m0, n0);
        __syncthreads();
    }
#pragma unroll
    for (int mt = 0; mt < 4; mt++) {
        int r0 = m0 + mt * 16 + g, r1 = r0 + 8;
        float bb0 = b1[r0], bb8 = b1[r1];
#pragma unroll
        for (int nt = 0; nt < 4; nt++) {
            int n = n0 + nt * 8 + tg * 2;
            Tsm[n * TRS + r0]       = gelu_exact(acc[mt][nt][0] + bb0);
            Tsm[(n + 1) * TRS + r0] = gelu_exact(acc[mt][nt][1] + bb0);
            Tsm[n * TRS + r1]       = gelu_exact(acc[mt][nt][2] + bb8);
            Tsm[(n + 1) * TRS + r1] = gelu_exact(acc[mt][nt][3] + bb8);
        }
    }
    __syncthreads();
    {
        int xq = tid >> 1;
        int jh = (tid & 1) * 64;
        float p = 0.f;
#pragma unroll 8
        for (int j = 0; j < 64; j++)
            p += Tsm[xq * TRS + jh + j] * w2s[jh + j];
        part[tid] = p;
        __syncthreads();
        if ((tid & 1) == 0) {
            size_t xi = (size_t)b * NN + xb + xq;
            out[xi] = (part[tid] + part[tid + 1] + b2[0]) * mask[xi];
        }
    }
}

// ---------------- launch ----------------
extern "C" void kernel_launch(void* const* d_in, const int* in_sizes, int n_in,
                              void* d_out, int out_size) {
    const float* x     = (const float*)d_in[0];
    const float* nodes = (const float*)d_in[1];
    const float* mask  = (const float*)d_in[2];
    const float* nw    = (const float*)d_in[3];
    const float* modes = (const float*)d_in[4];
    const float* fc0w  = (const float*)d_in[5];
    const float* fc0b  = (const float*)d_in[6];
    const float* wc    = (const float*)d_in[7];
    const float* ws_   = (const float*)d_in[8];
    const float* w0    = (const float*)d_in[9];
    const float* convw = (const float*)d_in[10];
    const float* convb = (const float*)d_in[11];
    const float* fc1w  = (const float*)d_in[12];
    const float* fc1b  = (const float*)d_in[13];
    const float* fc2w  = (const float*)d_in[14];
    const float* fc2b  = (const float*)d_in[15];
    float* out = (float*)d_out;

    const int INV_SMEM = 128 * TRS * 4;                    // 67584
    const int FC_SMEM  = 128 * TRS * 4 + (128 + 256) * 4;  // 69120
    cudaFuncSetAttribute(inv3, cudaFuncAttributeMaxDynamicSharedMemorySize, INV_SMEM);
    cudaFuncSetAttribute(fc1fc2, cudaFuncAttributeMaxDynamicSharedMemorySize, FC_SMEM);

    bf *pcp, *psp, *wbcp, *wbsp, *nch, *ncl, *hh0, *hl0;
    cudaGetSymbolAddress((void**)&pcp, g_pc);
    cudaGetSymbolAddress((void**)&psp, g_ps);
    cudaGetSymbolAddress((void**)&wbcp, g_wbc);
    cudaGetSymbolAddress((void**)&wbsp, g_wbs);
    cudaGetSymbolAddress((void**)&nch, g_nch);
    cudaGetSymbolAddress((void**)&ncl, g_ncl);
    cudaGetSymbolAddress((void**)&hh0, g_hcnh);
    cudaGetSymbolAddress((void**)&hl0, g_hcnl);
    bf* hh1 = hh0 + (size_t)BB*CC*NN;
    bf* hl1 = hl0 + (size_t)BB*CC*NN;

    bases_all<<<dim3(NN/32, BB), 256>>>(nodes, mask, nw, modes);
    fc0_kernel<<<(BB*CC*NN)/256, 256>>>(x, fc0w, fc0b, hh0, hl0);
    split_weights_kernel<<<(LL*CC*CC)/256, 256>>>(convw, fc1w);
    trans_split<<<dim3(NN/32, 4*BB), 256>>>(hh0, hl0);

    bf *ch = hh0, *cl = hl0, *oh = hh1, *ol = hl1;
    for (int l = 0; l < LL; l++) {
        gemm_fwd<<<dim3(NSPLIT, BB), 256>>>(ch, wbcp, pcp);
        gemm_fwd<<<dim3(NSPLIT, BB), 256>>>(ch, wbsp, psp);
        reduce_kernel<<<(BB*CC*KK)/2048, 256>>>();
        x0_kernel<<<dim3(CC, BB), 256>>>(ch, nw, mask);
        f0_kernel<<<BB, CC>>>(w0, l);
        mix_kernel<<<dim3(CC, BB), KK>>>(wc, ws_, l);
        inv3<<<dim3(NN/128, BB), 256, INV_SMEM>>>(nch, ncl, oh, ol, nch, ncl,
                                                  convb, mask, l, (l != LL-1) ? 1 : 0);
        bf* t;
        t = ch; ch = oh; oh = t;
        t = cl; cl = ol; ol = t;
    }
    fc1fc2<<<dim3(NN/128, BB), 256, FC_SMEM>>>(nch, ncl, fc1b, fc2w, fc2b, mask, out);
}

// round 14
// speedup vs baseline: 1.2008x; 1.0201x over previous
#include <cuda_runtime.h>
#include <cuda_bf16.h>
#include <cstdint>
#include <math.h>

#define BB 8
#define NN 16384
#define KK 128
#define CC 128
#define LL 4
#define NSPLIT 32
#define XS (NN / NSPLIT)   // 512
#define PAD 40
#define TSZ (128 * PAD)
#define TRS 132

typedef __nv_bfloat16 bf;

// ---------------- device scratch ----------------
__device__ bf g_bc[BB*NN*KK];
__device__ bf g_bs[BB*NN*KK];
__device__ bf g_wbc[BB*KK*NN];
__device__ bf g_wbs[BB*KK*NN];
__device__ bf g_hcnh[2][BB*CC*NN];               // hi only (lo is dead)
__device__ bf g_nch[BB*NN*CC], g_ncl[BB*NN*CC];
__device__ bf g_pc[NSPLIT*BB*CC*KK], g_ps[NSPLIT*BB*CC*KK];
__device__ float g_xc[BB*CC*KK], g_xs[BB*CC*KK];
__device__ float g_x0v[BB*CC], g_f0v[BB*CC];
__device__ bf g_fcw[BB*CC*KK];
__device__ bf g_fsw[BB*CC*KK];
__device__ bf g_cw_hi[LL*CC*CC], g_cw_lo[LL*CC*CC];
__device__ bf g_w1t_hi[CC*CC], g_w1t_lo[CC*CC];

// ---------------- helpers ----------------
__device__ __forceinline__ void split_bf(float v, bf& h, bf& l) {
    h = __float2bfloat16(v);
    l = __float2bfloat16(v - __bfloat162float(h));
}
__device__ __forceinline__ float gelu_exact(float v) {
    return 0.5f * v * (1.0f + erff(v * 0.70710678118654752f));
}
#define MMA(d, a0, a1, a2, a3, b0, b1) \
    asm volatile("mma.sync.aligned.m16n8k16.row.col.f32.bf16.bf16.f32 " \
        "{%0,%1,%2,%3}, {%4,%5,%6,%7}, {%8,%9}, {%0,%1,%2,%3};" \
        : "+f"((d)[0]), "+f"((d)[1]), "+f"((d)[2]), "+f"((d)[3]) \
        : "r"(a0), "r"(a1), "r"(a2), "r"(a3), "r"(b0), "r"(b1))

__device__ __forceinline__ void cp_tile(bf* dst, const bf* __restrict__ src, size_t ldm, int tid) {
#pragma unroll
    for (int j = 0; j < 2; j++) {
        int idx = tid + j * 256;
        int row = idx >> 2, q = idx & 3;
        *(uint4*)(dst + row * PAD + q * 8) = *(const uint4*)(src + (size_t)row * ldm + q * 8);
    }
}

__device__ __forceinline__ void gemm_chunk1(const bf* A, const bf* B,
                                            float acc[4][4][4], int g, int tg, int m0, int n0) {
#pragma unroll
    for (int ks = 0; ks < 32; ks += 16) {
        uint32_t bh[4][2];
#pragma unroll
        for (int nt = 0; nt < 4; nt++) {
            const bf* p = B + (n0 + nt * 8 + g) * PAD + ks + tg * 2;
            bh[nt][0] = *(const uint32_t*)p;
            bh[nt][1] = *(const uint32_t*)(p + 8);
        }
#pragma unroll
        for (int mt = 0; mt < 4; mt++) {
            const bf* p = A + (m0 + mt * 16 + g) * PAD + ks + tg * 2;
            uint32_t a0 = *(const uint32_t*)p;
            uint32_t a1 = *(const uint32_t*)(p + 8 * PAD);
            uint32_t a2 = *(const uint32_t*)(p + 8);
            uint32_t a3 = *(const uint32_t*)(p + 8 * PAD + 8);
#pragma unroll
            for (int nt = 0; nt < 4; nt++)
                MMA(acc[mt][nt], a0, a1, a2, a3, bh[nt][0], bh[nt][1]);
        }
    }
}

__device__ __forceinline__ void gemm_chunk3(const bf* Ah, const bf* Al, const bf* Bh, const bf* Bl,
                                            float acc[4][4][4], int g, int tg, int m0, int n0) {
#pragma unroll
    for (int ks = 0; ks < 32; ks += 16) {
        uint32_t bh[4][2], bl[4][2];
#pragma unroll
        for (int nt = 0; nt < 4; nt++) {
            const bf* p = Bh + (n0 + nt * 8 + g) * PAD + ks + tg * 2;
            bh[nt][0] = *(const uint32_t*)p;
            bh[nt][1] = *(const uint32_t*)(p + 8);
            const bf* q = Bl + (n0 + nt * 8 + g) * PAD + ks + tg * 2;
            bl[nt][0] = *(const uint32_t*)q;
            bl[nt][1] = *(const uint32_t*)(q + 8);
        }
#pragma unroll
        for (int mt = 0; mt < 4; mt++) {
            const bf* p = Ah + (m0 + mt * 16 + g) * PAD + ks + tg * 2;
            uint32_t ah0 = *(const uint32_t*)p;
            uint32_t ah1 = *(const uint32_t*)(p + 8 * PAD);
            uint32_t ah2 = *(const uint32_t*)(p + 8);
            uint32_t ah3 = *(const uint32_t*)(p + 8 * PAD + 8);
            const bf* q = Al + (m0 + mt * 16 + g) * PAD + ks + tg * 2;
            uint32_t al0 = *(const uint32_t*)q;
            uint32_t al1 = *(const uint32_t*)(q + 8 * PAD);
            uint32_t al2 = *(const uint32_t*)(q + 8);
            uint32_t al3 = *(const uint32_t*)(q + 8 * PAD + 8);
#pragma unroll
            for (int nt = 0; nt < 4; nt++) {
                MMA(acc[mt][nt], ah0, ah1, ah2, ah3, bh[nt][0], bh[nt][1]);
                MMA(acc[mt][nt], ah0, ah1, ah2, ah3, bl[nt][0], bl[nt][1]);
                MMA(acc[mt][nt], al0, al1, al2, al3, bh[nt][0], bh[nt][1]);
            }
        }
    }
}

// ---------------- merged bases producer ----------------
__global__ void bases_all(const float* __restrict__ nodes, const float* __restrict__ mask,
                          const float* __restrict__ nw, const float* __restrict__ modes) {
    __shared__ unsigned short Tc[KK*32], Tsn[KK*32];
    int n0 = blockIdx.x * 32, b = blockIdx.y, tid = threadIdx.x;
    for (int idx = tid; idx < 32 * KK; idx += 256) {
        int n = idx >> 7, k = idx & 127;
        int bn = b * NN + n0 + n;
        float m = mask[bn];
        float wgt = m * nw[bn];
        float t = nodes[bn*2] * __ldg(&modes[k*2]) + nodes[bn*2+1] * __ldg(&modes[k*2+1]);
        float s, c; sincosf(t, &s, &c);
        size_t o = (size_t)bn * KK + k;
        g_bc[o] = __float2bfloat16(c * m);
        g_bs[o] = __float2bfloat16(s * m);
        Tc[k * 32 + n]  = __bfloat16_as_ushort(__float2bfloat16(c * wgt));
        Tsn[k * 32 + n] = __bfloat16_as_ushort(__float2bfloat16(s * wgt));
    }
    __syncthreads();
    for (int idx = tid; idx < KK * 32; idx += 256) {
        int n = idx & 31, k = idx >> 5;
        size_t o = ((size_t)(b * KK + k)) * NN + n0 + n;
        g_wbc[o] = __ushort_as_bfloat16(Tc[k * 32 + n]);
        g_wbs[o] = __ushort_as_bfloat16(Tsn[k * 32 + n]);
    }
}
// fc0 fused: writes hnc (hi+lo) coalesced AND hcn_hi via padded smem transpose
__global__ void fc0_kernel(const float* __restrict__ x, const float* __restrict__ w,
                           const float* __restrict__ bias, bf* __restrict__ ohh) {
    __shared__ uint32_t T[32 * 133];
    int n0 = blockIdx.x * 32, b = blockIdx.y, tid = threadIdx.x;
    for (int idx = tid; idx < 32 * 128; idx += 256) {
        int n = idx >> 7, c = idx & 127;
        int bn = b * NN + n0 + n;
        const float* xp = x + (size_t)bn * 3;
        float v = bias[c] + xp[0]*w[c] + xp[1]*w[CC+c] + xp[2]*w[2*CC+c];
        bf hi, lo; split_bf(v, hi, lo);
        g_nch[(size_t)bn * CC + c] = hi;
        g_ncl[(size_t)bn * CC + c] = lo;
        T[n * 133 + c] = (uint32_t)__bfloat16_as_ushort(hi);
    }
    __syncthreads();
    for (int idx = tid; idx < 32 * 128; idx += 256) {
        int c = idx >> 5, n = idx & 31;
        ohh[((size_t)b * CC + c) * NN + n0 + n] =
            __ushort_as_bfloat16((unsigned short)T[n * 133 + c]);
    }
}
__global__ void split_weights_kernel(const float* __restrict__ convw, const float* __restrict__ fc1w) {
    int gid = blockIdx.x * blockDim.x + threadIdx.x;
    bf h, l;
    split_bf(convw[gid], h, l);
    g_cw_hi[gid] = h; g_cw_lo[gid] = l;
    if (gid < CC*CC) {
        int j = gid >> 7, c = gid & 127;
        split_bf(fc1w[c*CC + j], h, l);
        g_w1t_hi[gid] = h; g_w1t_lo[gid] = l;
    }
}

// ---------------- forward projection GEMM (bf16, double-buffered, bf16 partials) ----------------
__global__ __launch_bounds__(256, 2) void gemm_fwd(const bf* __restrict__ Ahg,
                                                   const bf* __restrict__ Bhg,
                                                   bf* __restrict__ outp) {
    __shared__ bf As[2][TSZ], Bs[2][TSZ];
    int split = blockIdx.x, b = blockIdx.y;
    int tid = threadIdx.x, w = tid >> 5, lane = tid & 31, g = lane >> 2, tg = lane & 3;
    int m0 = (w & 1) * 64, n0 = (w >> 1) * 32;
    const bf* As_g = Ahg + (size_t)b * CC * NN + (size_t)split * XS;
    const bf* Bs_g = Bhg + (size_t)b * KK * NN + (size_t)split * XS;
    float acc[4][4][4];
#pragma unroll
    for (int i = 0; i < 4; i++)
#pragma unroll
        for (int j = 0; j < 4; j++)
#pragma unroll
            for (int q = 0; q < 4; q++) acc[i][j][q] = 0.f;

    const int NCH = XS / 32;
    cp_tile(As[0], As_g, NN, tid);
    cp_tile(Bs[0], Bs_g, NN, tid);
    __syncthreads();
    for (int ch = 0; ch < NCH; ch++) {
        int cur = ch & 1;
        if (ch + 1 < NCH) {
            cp_tile(As[cur ^ 1], As_g + (ch + 1) * 32, NN, tid);
            cp_tile(Bs[cur ^ 1], Bs_g + (ch + 1) * 32, NN, tid);
        }
        gemm_chunk1(As[cur], Bs[cur], acc, g, tg, m0, n0);
        __syncthreads();
    }
    bf* pp = outp + (size_t)(split * BB + b) * CC * KK;
#pragma unroll
    for (int mt = 0; mt < 4; mt++) {
        int r0 = m0 + mt * 16 + g;
#pragma unroll
        for (int nt = 0; nt < 4; nt++) {
            int n = n0 + nt * 8 + tg * 2;
            uint32_t v0 = (uint32_t)__bfloat16_as_ushort(__float2bfloat16(acc[mt][nt][0]))
                        | ((uint32_t)__bfloat16_as_ushort(__float2bfloat16(acc[mt][nt][1])) << 16);
            uint32_t v1 = (uint32_t)__bfloat16_as_ushort(__float2bfloat16(acc[mt][nt][2]))
                        | ((uint32_t)__bfloat16_as_ushort(__float2bfloat16(acc[mt][nt][3])) << 16);
            *(uint32_t*)(pp + r0 * KK + n) = v0;
            *(uint32_t*)(pp + (r0 + 8) * KK + n) = v1;
        }
    }
}

// ---------------- fused inverse (double-buffered, 2 CTA/SM): spectral + conv ----------------
__global__ __launch_bounds__(256, 2) void inv3(const bf* __restrict__ hnc_hi, const bf* __restrict__ hnc_lo,
                                               bf* __restrict__ ohh,
                                               bf* __restrict__ onch, bf* __restrict__ oncl,
                                               const float* __restrict__ convb,
                                               const float* __restrict__ mask,
                                               int l, int apply_gelu) {
    extern __shared__ char dyns[];
    bf* tiles = (bf*)dyns;            // [2][4][TSZ]
    uint32_t* Tr = (uint32_t*)dyns;   // overlay after MMA
    int xb = blockIdx.x * 128, b = blockIdx.y;
    int tid = threadIdx.x, w = tid >> 5, lane = tid & 31, g = lane >> 2, tg = lane & 3;
    int m0 = (w & 1) * 64, n0 = (w >> 1) * 32;
    float acc[4][4][4];
#pragma unroll
    for (int i = 0; i < 4; i++)
#pragma unroll
        for (int j = 0; j < 4; j++)
#pragma unroll
            for (int q = 0; q < 4; q++) acc[i][j][q] = 0.f;

    const bf* pA01[2] = { g_fcw + (size_t)b*CC*KK, g_fsw + (size_t)b*CC*KK };
    const bf* pB01[2] = { g_bc + ((size_t)b*NN + xb)*KK, g_bs + ((size_t)b*NN + xb)*KK };
    const bf* cAh = g_cw_hi + (size_t)l*CC*CC;
    const bf* cAl = g_cw_lo + (size_t)l*CC*CC;
    const bf* cBh = hnc_hi + ((size_t)b*NN + xb)*CC;
    const bf* cBl = hnc_lo + ((size_t)b*NN + xb)*CC;

    auto load_step = [&](int s, int buf) {
        bf* base = tiles + (size_t)buf * 4 * TSZ;
        if (s < 8) {
            int pass = s >> 2, ch = s & 3;
            cp_tile(base + 0*TSZ, pA01[pass] + ch * 32, 128, tid);
            cp_tile(base + 2*TSZ, pB01[pass] + ch * 32, 128, tid);
        } else {
            int ch = s - 8;
            cp_tile(base + 0*TSZ, cAh + ch * 32, 128, tid);
            cp_tile(base + 1*TSZ, cAl + ch * 32, 128, tid);
            cp_tile(base + 2*TSZ, cBh + ch * 32, 128, tid);
            cp_tile(base + 3*TSZ, cBl + ch * 32, 128, tid);
        }
    };
    load_step(0, 0);
    __syncthreads();
    for (int s = 0; s < 12; s++) {
        int cur = s & 1;
        if (s + 1 < 12) load_step(s + 1, cur ^ 1);
        bf* base = tiles + (size_t)cur * 4 * TSZ;
        if (s < 8) gemm_chunk1(base, base + 2*TSZ, acc, g, tg, m0, n0);
        else gemm_chunk3(base, base + TSZ, base + 2*TSZ, base + 3*TSZ, acc, g, tg, m0, n0);
        __syncthreads();
    }
#pragma unroll
    for (int mt = 0; mt < 4; mt++) {
        int r0 = m0 + mt * 16 + g, r1 = r0 + 8;
        float cb0 = convb[l * CC + r0], f00 = g_f0v[b * CC + r0];
        float cb1 = convb[l * CC + r1], f01 = g_f0v[b * CC + r1];
#pragma unroll
        for (int nt = 0; nt < 4; nt++) {
            int n = n0 + nt * 8 + tg * 2;
            float mk0 = mask[(size_t)b * NN + xb + n];
            float mk1 = mask[(size_t)b * NN + xb + n + 1];
            float v00 = acc[mt][nt][0] + cb0 + f00 * mk0;
            float v01 = acc[mt][nt][1] + cb0 + f00 * mk1;
            float v10 = acc[mt][nt][2] + cb1 + f01 * mk0;
            float v11 = acc[mt][nt][3] + cb1 + f01 * mk1;
            if (apply_gelu) {
                v00 = gelu_exact(v00); v01 = gelu_exact(v01);
                v10 = gelu_exact(v10); v11 = gelu_exact(v11);
            }
            bf h00, l00, h01, l01, h10, l10, h11, l11;
            split_bf(v00, h00, l00); split_bf(v01, h01, l01);
            split_bf(v10, h10, l10); split_bf(v11, h11, l11);
            uint32_t p00 = (uint32_t)__bfloat16_as_ushort(h00) | ((uint32_t)__bfloat16_as_ushort(l00) << 16);
            uint32_t p01 = (uint32_t)__bfloat16_as_ushort(h01) | ((uint32_t)__bfloat16_as_ushort(l01) << 16);
            uint32_t p10 = (uint32_t)__bfloat16_as_ushort(h10) | ((uint32_t)__bfloat16_as_ushort(l10) << 16);
            uint32_t p11 = (uint32_t)__bfloat16_as_ushort(h11) | ((uint32_t)__bfloat16_as_ushort(l11) << 16);
            if (apply_gelu) {   // hcn_hi consumed only by next layer's gemm_fwd/x0
                size_t o0 = ((size_t)b * CC + r0) * NN + xb + n;
                size_t o1 = ((size_t)b * CC + r1) * NN + xb + n;
                *(uint32_t*)(ohh + o0) = (uint32_t)__bfloat16_as_ushort(h00) | ((uint32_t)__bfloat16_as_ushort(h01) << 16);
                *(uint32_t*)(ohh + o1) = (uint32_t)__bfloat16_as_ushort(h10) | ((uint32_t)__bfloat16_as_ushort(h11) << 16);
            }
            Tr[n * TRS + r0]       = p00;
            Tr[(n + 1) * TRS + r0] = p01;
            Tr[n * TRS + r1]       = p10;
            Tr[(n + 1) * TRS + r1] = p11;
        }
    }
    __syncthreads();
    {
        int xq = tid >> 1;
        int c0t = (tid & 1) * 64;
        size_t ob = ((size_t)b * NN + xb + xq) * CC + c0t;
#pragma unroll
        for (int q = 0; q < 8; q++) {
            __align__(16) unsigned short hh8[8], ll8[8];
#pragma unroll
            for (int c = 0; c < 8; c++) {
                uint32_t v = Tr[xq * TRS + c0t + q * 8 + c];
                hh8[c] = (unsigned short)(v & 0xffff);
                ll8[c] = (unsigned short)(v >> 16);
            }
            *(uint4*)(onch + ob + q * 8) = *(uint4*)hh8;
            *(uint4*)(oncl + ob + q * 8) = *(uint4*)ll8;
        }
    }
}

// ---------------- small kernels ----------------
__global__ void reduce_kernel() {
    int gid = (blockIdx.x * blockDim.x + threadIdx.x) * 8;
    float sc[8], ss[8];
#pragma unroll
    for (int q = 0; q < 8; q++) { sc[q] = 0.f; ss[q] = 0.f; }
#pragma unroll
    for (int s = 0; s < NSPLIT; s++) {
        uint4 a = *(const uint4*)&g_pc[(size_t)s * BB * CC * KK + gid];
        uint4 c = *(const uint4*)&g_ps[(size_t)s * BB * CC * KK + gid];
        const uint32_t* ap = (const uint32_t*)&a;
        const uint32_t* cp = (const uint32_t*)&c;
#pragma unroll
        for (int q = 0; q < 4; q++) {
            sc[q*2]   += __bfloat162float(__ushort_as_bfloat16((unsigned short)(ap[q] & 0xffff)));
            sc[q*2+1] += __bfloat162float(__ushort_as_bfloat16((unsigned short)(ap[q] >> 16)));
            ss[q*2]   += __bfloat162float(__ushort_as_bfloat16((unsigned short)(cp[q] & 0xffff)));
            ss[q*2+1] += __bfloat162float(__ushort_as_bfloat16((unsigned short)(cp[q] >> 16)));
        }
    }
#pragma unroll
    for (int q = 0; q < 8; q += 4) {
        *(float4*)&g_xc[gid + q] = make_float4(sc[q], sc[q+1], sc[q+2], sc[q+3]);
        *(float4*)&g_xs[gid + q] = make_float4(-ss[q], -ss[q+1], -ss[q+2], -ss[q+3]);
    }
}
__global__ void x0_kernel(const bf* __restrict__ hh,
                          const float* __restrict__ nw, const float* __restrict__ mask) {
    int i = blockIdx.x, b = blockIdx.y;
    const bf* rh = hh + ((size_t)b * CC + i) * NN;
    const float* nwb = nw + b * NN;
    const float* mb = mask + b * NN;
    float acc = 0.f;
    for (int x = threadIdx.x; x < NN; x += 256)
        acc += __bfloat162float(rh[x]) * nwb[x] * mb[x];
    __shared__ float red[256];
    red[threadIdx.x] = acc;
    __syncthreads();
    for (int s = 128; s > 0; s >>= 1) {
        if (threadIdx.x < s) red[threadIdx.x] += red[threadIdx.x + s];
        __syncthreads();
    }
    if (threadIdx.x == 0) g_x0v[b * CC + i] = red[0];
}
__global__ void f0_kernel(const float* __restrict__ w0, int l) {
    int b = blockIdx.x, o = threadIdx.x;
    __shared__ float xs[CC];
    xs[o] = g_x0v[b * CC + o];
    __syncthreads();
    const float* w = w0 + (size_t)l * CC * CC;
    float acc = 0.f;
#pragma unroll 8
    for (int i = 0; i < CC; i++) acc += xs[i] * w[i * CC + o];
    g_f0v[b * CC + o] = acc;
}
__global__ void mix_kernel(const float* __restrict__ wc, const float* __restrict__ ws, int l) {
    int o = blockIdx.x, b = blockIdx.y, k = threadIdx.x;
    const float* wcl = wc + (size_t)l * CC * CC * KK;
    const float* wsl = ws + (size_t)l * CC * CC * KK;
    float fcA = 0.f, fsA = 0.f;
#pragma unroll 4
    for (int i = 0; i < CC; i++) {
        float xc = g_xc[(b * CC + i) * KK + k];
        float xv = g_xs[(b * CC + i) * KK + k];
        float wcv = wcl[((size_t)i * CC + o) * KK + k];
        float wsv = wsl[((size_t)i * CC + o) * KK + k];
        fcA += xc * wcv - xv * wsv;
        fsA += xv * wcv + xc * wsv;
    }
    int idx = (b * CC + o) * KK + k;
    g_fcw[idx] = __float2bfloat16(2.0f * fcA);
    g_fsw[idx] = __float2bfloat16(-2.0f * fsA);
}

// ---------------- fused fc1 (MMA split, double-buffered) + fc2 + mask ----------------
__global__ __launch_bounds__(256, 2) void fc1fc2(const bf* __restrict__ hnc_hi, const bf* __restrict__ hnc_lo,
                                                 const float* __restrict__ b1,
                                                 const float* __restrict__ w2,
                                                 const float* __restrict__ b2,
                                                 const float* __restrict__ mask,
                                                 float* __restrict__ out) {
    extern __shared__ char dyns[];
    bf* tiles = (bf*)dyns;            // [2][4][TSZ]
    float* Tsm = (float*)dyns;        // overlay after MMA
    float* w2s = (float*)(dyns + 2 * 4 * TSZ * sizeof(bf));
    float* part = w2s + 128;
    int xb = blockIdx.x * 128, b = blockIdx.y;
    int tid = threadIdx.x, w = tid >> 5, lane = tid & 31, g = lane >> 2, tg = lane & 3;
    int m0 = (w & 1) * 64, n0 = (w >> 1) * 32;
    if (tid < 128) w2s[tid] = w2[tid];
    const bf* pBh = hnc_hi + ((size_t)b * NN + xb) * CC;
    const bf* pBl = hnc_lo + ((size_t)b * NN + xb) * CC;
    float acc[4][4][4];
#pragma unroll
    for (int i = 0; i < 4; i++)
#pragma unroll
        for (int j = 0; j < 4; j++)
#pragma unroll
            for (int q = 0; q < 4; q++) acc[i][j][q] = 0.f;

    auto load_step = [&](int ch, int buf) {
        bf* base = tiles + (size_t)buf * 4 * TSZ;
        cp_tile(base + 0*TSZ, g_w1t_hi + ch * 32, 128, tid);
        cp_tile(base + 1*TSZ, g_w1t_lo + ch * 32, 128, tid);
        cp_tile(base + 2*TSZ, pBh + ch * 32, 128, tid);
        cp_tile(base + 3*TSZ, pBl + ch * 32, 128, tid);
    };
    load_step(0, 0);
    __syncthreads();
    for (int ch = 0; ch < 4; ch++) {
        int cur = ch & 1;
        if (ch + 1 < 4) load_step(ch + 1, cur ^ 1);
        bf* base = tiles + (size_t)cur * 4 * TSZ;
        gemm_chunk3(base, base + TSZ, base + 2*TSZ, base + 3*TSZ, acc, g, tg, m0, n0);
        __syncthreads();
    }
#pragma unroll
    for (int mt = 0; mt < 4; mt++) {
        int r0 = m0 + mt * 16 + g, r1 = r0 + 8;
        float bb0 = b1[r0], bb8 = b1[r1];
#pragma unroll
        for (int nt = 0; nt < 4; nt++) {
            int n = n0 + nt * 8 + tg * 2;
            Tsm[n * TRS + r0]       = gelu_exact(acc[mt][nt][0] + bb0);
            Tsm[(n + 1) * TRS + r0] = gelu_exact(acc[mt][nt][1] + bb0);
            Tsm[n * TRS + r1]       = gelu_exact(acc[mt][nt][2] + bb8);
            Tsm[(n + 1) * TRS + r1] = gelu_exact(acc[mt][nt][3] + bb8);
        }
    }
    __syncthreads();
    {
        int xq = tid >> 1;
        int jh = (tid & 1) * 64;
        float p = 0.f;
#pragma unroll 8
        for (int j = 0; j < 64; j++)
            p += Tsm[xq * TRS + jh + j] * w2s[jh + j];
        part[tid] = p;
        __syncthreads();
        if ((tid & 1) == 0) {
            size_t xi = (size_t)b * NN + xb + xq;
            out[xi] = (part[tid] + part[tid + 1] + b2[0]) * mask[xi];
        }
    }
}

// ---------------- launch ----------------
extern "C" void kernel_launch(void* const* d_in, const int* in_sizes, int n_in,
                              void* d_out, int out_size) {
    const float* x     = (const float*)d_in[0];
    const float* nodes = (const float*)d_in[1];
    const float* mask  = (const float*)d_in[2];
    const float* nw    = (const float*)d_in[3];
    const float* modes = (const float*)d_in[4];
    const float* fc0w  = (const float*)d_in[5];
    const float* fc0b  = (const float*)d_in[6];
    const float* wc    = (const float*)d_in[7];
    const float* ws_   = (const float*)d_in[8];
    const float* w0    = (const float*)d_in[9];
    const float* convw = (const float*)d_in[10];
    const float* convb = (const float*)d_in[11];
    const float* fc1w  = (const float*)d_in[12];
    const float* fc1b  = (const float*)d_in[13];
    const float* fc2w  = (const float*)d_in[14];
    const float* fc2b  = (const float*)d_in[15];
    float* out = (float*)d_out;

    const int INV_SMEM = 2 * 4 * TSZ * 2;                   // 81920 (>= Tr 67584)
    const int FC_SMEM  = 2 * 4 * TSZ * 2 + (128 + 256) * 4; // 83456
    cudaFuncSetAttribute(inv3, cudaFuncAttributeMaxDynamicSharedMemorySize, INV_SMEM);
    cudaFuncSetAttribute(fc1fc2, cudaFuncAttributeMaxDynamicSharedMemorySize, FC_SMEM);

    bf *pcp, *psp, *wbcp, *wbsp, *nch, *ncl, *hh0;
    cudaGetSymbolAddress((void**)&pcp, g_pc);
    cudaGetSymbolAddress((void**)&psp, g_ps);
    cudaGetSymbolAddress((void**)&wbcp, g_wbc);
    cudaGetSymbolAddress((void**)&wbsp, g_wbs);
    cudaGetSymbolAddress((void**)&nch, g_nch);
    cudaGetSymbolAddress((void**)&ncl, g_ncl);
    cudaGetSymbolAddress((void**)&hh0, g_hcnh);
    bf* hh1 = hh0 + (size_t)BB*CC*NN;

    bases_all<<<dim3(NN/32, BB), 256>>>(nodes, mask, nw, modes);
    fc0_kernel<<<dim3(NN/32, BB), 256>>>(x, fc0w, fc0b, hh0);
    split_weights_kernel<<<(LL*CC*CC)/256, 256>>>(convw, fc1w);

    bf *ch = hh0, *oh = hh1;
    for (int l = 0; l < LL; l++) {
        gemm_fwd<<<dim3(NSPLIT, BB), 256>>>(ch, wbcp, pcp);
        gemm_fwd<<<dim3(NSPLIT, BB), 256>>>(ch, wbsp, psp);
        reduce_kernel<<<(BB*CC*KK)/2048, 256>>>();
        x0_kernel<<<dim3(CC, BB), 256>>>(ch, nw, mask);
        f0_kernel<<<BB, CC>>>(w0, l);
        mix_kernel<<<dim3(CC, BB), KK>>>(wc, ws_, l);
        inv3<<<dim3(NN/128, BB), 256, INV_SMEM>>>(nch, ncl, oh, nch, ncl,
                                                  convb, mask, l, (l != LL-1) ? 1 : 0);
        bf* t = ch; ch = oh; oh = t;
    }
    fc1fc2<<<dim3(NN/128, BB), 256, FC_SMEM>>>(nch, ncl, fc1b, fc2w, fc2b, mask, out);
}